// round 3
// baseline (speedup 1.0000x reference)
#include <cuda_runtime.h>

#define B_SZ   2
#define S_LEN  2048
#define DM     1024
#define NH     16
#define DKH    64
#define M_ROWS (B_SZ * S_LEN)   // 4096

typedef unsigned long long u64;

// ---- packed f32x2 helpers (SASS FFMA2 path) --------------------------------
__device__ __forceinline__ u64 pk2(float lo, float hi) {
    u64 r; asm("mov.b64 %0, {%1,%2};" : "=l"(r) : "f"(lo), "f"(hi)); return r;
}
__device__ __forceinline__ u64 dup2(float x) { return pk2(x, x); }
__device__ __forceinline__ void upk2(u64 v, float& lo, float& hi) {
    asm("mov.b64 {%0,%1}, %2;" : "=f"(lo), "=f"(hi) : "l"(v));
}
__device__ __forceinline__ u64 fma2(u64 a, u64 b, u64 c) {
    u64 d; asm("fma.rn.f32x2 %0, %1, %2, %3;" : "=l"(d) : "l"(a), "l"(b), "l"(c)); return d;
}
__device__ __forceinline__ u64 mul2(u64 a, u64 b) {
    u64 d; asm("mul.rn.f32x2 %0, %1, %2;" : "=l"(d) : "l"(a), "l"(b)); return d;
}

// Scratch: split-head Q/K/V [B*H, S, d_k] and attention output [B*S, D]
__device__ __align__(16) float g_q[(size_t)B_SZ * NH * S_LEN * DKH];
__device__ __align__(16) float g_k[(size_t)B_SZ * NH * S_LEN * DKH];
__device__ __align__(16) float g_v[(size_t)B_SZ * NH * S_LEN * DKH];
__device__ __align__(16) float g_ao[(size_t)M_ROWS * DM];

// ---------------------------------------------------------------------------
// GEMM: Y = X @ W^T + bias, 128x128xK8 tile, 256 threads, 8x8 per thread,
// inner product via packed FFMA2 (acc pairs along n).
// ---------------------------------------------------------------------------
template <int MODE>
__global__ void __launch_bounds__(256)
gemm_xwt(const float* __restrict__ Xin, const float* __restrict__ W,
         const float* __restrict__ bias, float* __restrict__ Yout)
{
    __shared__ float As[8][128];   // As[k][m]
    __shared__ float Bs[8][128];   // Bs[k][n]

    const float* X = (MODE == 3) ? (const float*)g_ao : Xin;

    const int tid = threadIdx.x;
    const int tx  = tid & 15;
    const int ty  = tid >> 4;
    const int bm  = blockIdx.y << 7;
    const int bn  = blockIdx.x << 7;

    const int lr = tid >> 1;         // 0..127
    const int lc = (tid & 1) << 2;   // 0 or 4

    const float* Xp = X + (size_t)(bm + lr) * DM + lc;
    const float* Wp = W + (size_t)(bn + lr) * DM + lc;

    u64 acc2[8][4];
#pragma unroll
    for (int i = 0; i < 8; i++)
#pragma unroll
        for (int jp = 0; jp < 4; jp++) acc2[i][jp] = 0ull;

    for (int k0 = 0; k0 < DM; k0 += 8) {
        float4 xa = *(const float4*)(Xp + k0);
        float4 wa = *(const float4*)(Wp + k0);
        if (k0) __syncthreads();
        As[lc + 0][lr] = xa.x; As[lc + 1][lr] = xa.y;
        As[lc + 2][lr] = xa.z; As[lc + 3][lr] = xa.w;
        Bs[lc + 0][lr] = wa.x; Bs[lc + 1][lr] = wa.y;
        Bs[lc + 2][lr] = wa.z; Bs[lc + 3][lr] = wa.w;
        __syncthreads();
#pragma unroll
        for (int kk = 0; kk < 8; kk++) {
            float4 a0 = *(const float4*)&As[kk][(ty << 2)];
            float4 a1 = *(const float4*)&As[kk][(ty << 2) + 64];
            float4 b0 = *(const float4*)&Bs[kk][(tx << 2)];
            float4 b1 = *(const float4*)&Bs[kk][(tx << 2) + 64];
            u64 bp[4] = { pk2(b0.x, b0.y), pk2(b0.z, b0.w),
                          pk2(b1.x, b1.y), pk2(b1.z, b1.w) };
            float av[8] = {a0.x, a0.y, a0.z, a0.w, a1.x, a1.y, a1.z, a1.w};
#pragma unroll
            for (int i = 0; i < 8; i++) {
                u64 ad = dup2(av[i]);
#pragma unroll
                for (int jp = 0; jp < 4; jp++)
                    acc2[i][jp] = fma2(ad, bp[jp], acc2[i][jp]);
            }
        }
    }

    float acc[8][8];
#pragma unroll
    for (int i = 0; i < 8; i++)
#pragma unroll
        for (int jp = 0; jp < 4; jp++)
            upk2(acc2[i][jp], acc[i][jp * 2], acc[i][jp * 2 + 1]);

#pragma unroll
    for (int i = 0; i < 8; i++) {
        const int m = bm + (ty << 2) + (i & 3) + ((i >> 2) << 6);
#pragma unroll
        for (int j = 0; j < 8; j++) {
            const int n = bn + (tx << 2) + (j & 3) + ((j >> 2) << 6);
            float val = acc[i][j] + bias[n];
            if (MODE <= 2) {
                const int b = m >> 11;
                const int s = m & (S_LEN - 1);
                const int h = n >> 6;
                const int d = n & 63;
                float* dst = (MODE == 0) ? g_q : (MODE == 1) ? g_k : g_v;
                dst[(((size_t)(b * NH + h) * S_LEN) + s) * DKH + d] = val;
            } else {
                Yout[(size_t)m * DM + n] = val;
            }
        }
    }
}

// ---------------------------------------------------------------------------
// Flash attention v2: CTA = (bh, 128-query tile), KV tiles of 128.
// 256 threads (16x16), 8x8 S micro-tile, packed FFMA2, exp2-domain softmax.
// Dynamic smem 160KB: Qs[128x64] Ks[128x64] Vs[128x64] Ps[128x128].
// ---------------------------------------------------------------------------
#define ATTN_SMEM (160 * 1024)

__global__ void __launch_bounds__(256, 1)
attn_fwd()
{
    extern __shared__ float sm[];
    float*  Qs = sm;            //  8192 floats
    float*  Ks = sm + 8192;
    float*  Vs = sm + 16384;
    float*  Ps = sm + 24576;    // 16384 floats
    float4* Q4 = (float4*)Qs;
    float4* K4 = (float4*)Ks;
    float4* V4 = (float4*)Vs;
    float4* P4 = (float4*)Ps;

    const int tid = threadIdx.x;
    const int tx  = tid & 15;
    const int ty  = tid >> 4;
    const int bh  = blockIdx.y;          // 0..31
    const int q0  = blockIdx.x << 7;

    const float* Qb = g_q + (size_t)bh * S_LEN * DKH;
    const float* Kb = g_k + (size_t)bh * S_LEN * DKH;
    const float* Vb = g_v + (size_t)bh * S_LEN * DKH;

    // scale folded into Q: 1/sqrt(64) * log2(e)  (softmax runs in exp2 domain)
    const float SCALE = 0.125f * 1.44269504088896340736f;

    // Load Q tile (pre-scaled)
#pragma unroll
    for (int p = 0; p < 8; p++) {
        int idx = tid + (p << 8);
        int r   = idx >> 4;
        int d4  = idx & 15;
        float4 qv = ((const float4*)(Qb + (size_t)(q0 + r) * DKH))[d4];
        qv.x *= SCALE; qv.y *= SCALE; qv.z *= SCALE; qv.w *= SCALE;
        Q4[(r << 4) + d4] = qv;
    }

    float m_r[8], l_r[8];
    u64   o2[8][2];
#pragma unroll
    for (int i = 0; i < 8; i++) {
        m_r[i] = -1e30f; l_r[i] = 0.0f;
        o2[i][0] = 0ull; o2[i][1] = 0ull;
    }

    for (int kt = 0; kt < S_LEN; kt += 128) {
        __syncthreads();   // prev PV done with Ps/Vs; Ks free
        // Load K (swizzled) and V tiles
#pragma unroll
        for (int p = 0; p < 8; p++) {
            int idx = tid + (p << 8);
            int r   = idx >> 4;
            int d4  = idx & 15;
            float4 kv = ((const float4*)(Kb + (size_t)(kt + r) * DKH))[d4];
            float4 vv = ((const float4*)(Vb + (size_t)(kt + r) * DKH))[d4];
            K4[(r << 4) + (d4 ^ (r >> 3))] = kv;
            V4[(r << 4) + d4]              = vv;
        }
        __syncthreads();

        // ---- S = Q K^T : sacc2[i][jp] packs cols (2jp, 2jp+1) of tx*8.. ----
        u64 sacc2[8][4];
#pragma unroll
        for (int i = 0; i < 8; i++)
#pragma unroll
            for (int jp = 0; jp < 4; jp++) sacc2[i][jp] = 0ull;

#pragma unroll 4
        for (int d0 = 0; d0 < 64; d0 += 4) {
            const int dg = d0 >> 2;
            float4 aq[8];
#pragma unroll
            for (int i = 0; i < 8; i++)
                aq[i] = Q4[((ty * 8 + i) << 4) + dg];
            u64 bp[4][4];
#pragma unroll
            for (int jp = 0; jp < 4; jp++) {
                int c0 = tx * 8 + jp * 2;
                float4 b0 = K4[(c0 << 4) + (dg ^ tx)];
                float4 b1 = K4[((c0 + 1) << 4) + (dg ^ tx)];
                bp[jp][0] = pk2(b0.x, b1.x);
                bp[jp][1] = pk2(b0.y, b1.y);
                bp[jp][2] = pk2(b0.z, b1.z);
                bp[jp][3] = pk2(b0.w, b1.w);
            }
#pragma unroll
            for (int i = 0; i < 8; i++) {
                const float* af = (const float*)&aq[i];
#pragma unroll
                for (int dd = 0; dd < 4; dd++) {
                    u64 ad = dup2(af[dd]);
#pragma unroll
                    for (int jp = 0; jp < 4; jp++)
                        sacc2[i][jp] = fma2(ad, bp[jp][dd], sacc2[i][jp]);
                }
            }
        }

        // ---- online softmax (exp2 domain) + P store ----
#pragma unroll
        for (int i = 0; i < 8; i++) {
            float s[8];
#pragma unroll
            for (int jp = 0; jp < 4; jp++)
                upk2(sacc2[i][jp], s[2 * jp], s[2 * jp + 1]);
            float mx = s[0];
#pragma unroll
            for (int j = 1; j < 8; j++) mx = fmaxf(mx, s[j]);
#pragma unroll
            for (int off = 8; off >= 1; off >>= 1)
                mx = fmaxf(mx, __shfl_xor_sync(0xffffffffu, mx, off));
            float newm = fmaxf(m_r[i], mx);
            float p[8], rs = 0.0f;
#pragma unroll
            for (int j = 0; j < 8; j++) { p[j] = exp2f(s[j] - newm); rs += p[j]; }
#pragma unroll
            for (int off = 8; off >= 1; off >>= 1)
                rs += __shfl_xor_sync(0xffffffffu, rs, off);
            float corr = exp2f(m_r[i] - newm);
            l_r[i] = l_r[i] * corr + rs;
            m_r[i] = newm;
            u64 c2 = dup2(corr);
            o2[i][0] = mul2(o2[i][0], c2);
            o2[i][1] = mul2(o2[i][1], c2);

            int row = ty * 8 + i;
            int sw  = (row >> 3) & 3;
            int kg0 = 2 * tx, kg1 = 2 * tx + 1;
            P4[(row << 5) + (kg0 ^ ((kg0 >> 3) & 3) ^ sw)] = make_float4(p[0], p[1], p[2], p[3]);
            P4[(row << 5) + (kg1 ^ ((kg1 >> 3) & 3) ^ sw)] = make_float4(p[4], p[5], p[6], p[7]);
        }
        __syncthreads();   // Ps complete (also: everyone past QK, Ks free)

        // ---- O += P V : o cols tx*4..+3 (2 pairs) ----
#pragma unroll 4
        for (int c0 = 0; c0 < 128; c0 += 4) {
            const int kg = c0 >> 2;
            float4 ap[8];
#pragma unroll
            for (int i = 0; i < 8; i++) {
                int row = ty * 8 + i;
                ap[i] = P4[(row << 5) + (kg ^ ((kg >> 3) & 3) ^ ((row >> 3) & 3))];
            }
            float4 vv[4];
#pragma unroll
            for (int t = 0; t < 4; t++)
                vv[t] = V4[((c0 + t) << 4) + tx];
#pragma unroll
            for (int t = 0; t < 4; t++) {
                u64 v0 = pk2(vv[t].x, vv[t].y);
                u64 v1 = pk2(vv[t].z, vv[t].w);
#pragma unroll
                for (int i = 0; i < 8; i++) {
                    const float* af = (const float*)&ap[i];
                    u64 ad = dup2(af[t]);
                    o2[i][0] = fma2(ad, v0, o2[i][0]);
                    o2[i][1] = fma2(ad, v1, o2[i][1]);
                }
            }
        }
    }

    // Epilogue: normalize, write [B, S, H*d_k] into g_ao
    const int b = bh >> 4;
    const int h = bh & 15;
#pragma unroll
    for (int i = 0; i < 8; i++) {
        float inv = 1.0f / l_r[i];
        float o0, o1, o2a, o3;
        upk2(o2[i][0], o0, o1);
        upk2(o2[i][1], o2a, o3);
        int srow = q0 + ty * 8 + i;
        float4 ov = make_float4(o0 * inv, o1 * inv, o2a * inv, o3 * inv);
        *(float4*)(g_ao + ((size_t)(b * S_LEN + srow)) * DM + (h << 6) + (tx << 2)) = ov;
    }
}

// ---------------------------------------------------------------------------
extern "C" void kernel_launch(void* const* d_in, const int* in_sizes, int n_in,
                              void* d_out, int out_size)
{
    const float* q  = (const float*)d_in[0];
    const float* k  = (const float*)d_in[1];
    const float* v  = (const float*)d_in[2];
    const float* wq = (const float*)d_in[3];
    const float* bq = (const float*)d_in[4];
    const float* wk = (const float*)d_in[5];
    const float* bk = (const float*)d_in[6];
    const float* wv = (const float*)d_in[7];
    const float* bv = (const float*)d_in[8];
    const float* wo = (const float*)d_in[9];
    const float* bo = (const float*)d_in[10];
    float* out = (float*)d_out;

    // idempotent; non-stream API (capture-safe)
    cudaFuncSetAttribute(attn_fwd, cudaFuncAttributeMaxDynamicSharedMemorySize, ATTN_SMEM);

    dim3 gg(DM / 128, M_ROWS / 128);   // (8, 32)
    gemm_xwt<0><<<gg, 256>>>(q, wq, bq, nullptr);
    gemm_xwt<1><<<gg, 256>>>(k, wk, bk, nullptr);
    gemm_xwt<2><<<gg, 256>>>(v, wv, bv, nullptr);
    attn_fwd<<<dim3(S_LEN / 128, B_SZ * NH), 256, ATTN_SMEM>>>();
    gemm_xwt<3><<<gg, 256>>>(nullptr, wo, bo, out);
}

// round 5
// speedup vs baseline: 1.4437x; 1.4437x over previous
#include <cuda_runtime.h>
#include <cuda_bf16.h>
#include <cstdint>

#define B_SZ   2
#define S_LEN  2048
#define DM     1024
#define NH     16
#define DKH    64
#define M_ROWS (B_SZ * S_LEN)   // 4096

// ---------------- scratch ----------------------------------------------------
__device__ __align__(16) float g_q [(size_t)B_SZ * NH * S_LEN * DKH];
__device__ __align__(16) float g_k [(size_t)B_SZ * NH * S_LEN * DKH];
__device__ __align__(16) float g_v [(size_t)B_SZ * NH * S_LEN * DKH];
__device__ __align__(16) float g_ao[(size_t)M_ROWS * DM];
// bf16 hi/lo split buffers
__device__ __align__(16) __nv_bfloat16 g_xh[(size_t)M_ROWS * DM];
__device__ __align__(16) __nv_bfloat16 g_xl[(size_t)M_ROWS * DM];
__device__ __align__(16) __nv_bfloat16 g_wh[(size_t)DM * DM];
__device__ __align__(16) __nv_bfloat16 g_wl[(size_t)DM * DM];

// ---------------- helpers -----------------------------------------------------
__device__ __forceinline__ uint32_t smem_u32(const void* p) {
    uint32_t a;
    asm("{ .reg .u64 t; cvta.to.shared.u64 t, %1; cvt.u32.u64 %0, t; }"
        : "=r"(a) : "l"(p));
    return a;
}
__device__ __forceinline__ void cpa16(uint32_t s, const void* g) {
    asm volatile("cp.async.cg.shared.global [%0], [%1], 16;" :: "r"(s), "l"(g) : "memory");
}
__device__ __forceinline__ void ldsm4(uint32_t r[4], uint32_t addr) {
    asm volatile("ldmatrix.sync.aligned.m8n8.x4.shared.b16 {%0,%1,%2,%3}, [%4];"
                 : "=r"(r[0]), "=r"(r[1]), "=r"(r[2]), "=r"(r[3]) : "r"(addr));
}
__device__ __forceinline__ void mma_bf16(float d[4], const uint32_t a[4],
                                         uint32_t b0, uint32_t b1) {
    asm volatile(
        "mma.sync.aligned.m16n8k16.row.col.f32.bf16.bf16.f32 "
        "{%0,%1,%2,%3},{%4,%5,%6,%7},{%8,%9},{%0,%1,%2,%3};"
        : "+f"(d[0]), "+f"(d[1]), "+f"(d[2]), "+f"(d[3])
        : "r"(a[0]), "r"(a[1]), "r"(a[2]), "r"(a[3]), "r"(b0), "r"(b1));
}

// ---------------- fp32 -> bf16 hi/lo split -----------------------------------
template <int DST, int SRC_AO>
__global__ void __launch_bounds__(256)
conv_split(const float4* __restrict__ x, int n4)
{
    if (SRC_AO) x = (const float4*)g_ao;
    __nv_bfloat162* hi = (DST == 0) ? (__nv_bfloat162*)g_xh : (__nv_bfloat162*)g_wh;
    __nv_bfloat162* lo = (DST == 0) ? (__nv_bfloat162*)g_xl : (__nv_bfloat162*)g_wl;
    int i = blockIdx.x * 256 + threadIdx.x;
    if (i >= n4) return;
    float4 v = x[i];
    __nv_bfloat16 h0 = __float2bfloat16(v.x);
    __nv_bfloat16 h1 = __float2bfloat16(v.y);
    __nv_bfloat16 h2 = __float2bfloat16(v.z);
    __nv_bfloat16 h3 = __float2bfloat16(v.w);
    __nv_bfloat16 l0 = __float2bfloat16(v.x - __bfloat162float(h0));
    __nv_bfloat16 l1 = __float2bfloat16(v.y - __bfloat162float(h1));
    __nv_bfloat16 l2 = __float2bfloat16(v.z - __bfloat162float(h2));
    __nv_bfloat16 l3 = __float2bfloat16(v.w - __bfloat162float(h3));
    hi[i * 2 + 0] = __nv_bfloat162(h0, h1);
    hi[i * 2 + 1] = __nv_bfloat162(h2, h3);
    lo[i * 2 + 0] = __nv_bfloat162(l0, l1);
    lo[i * 2 + 1] = __nv_bfloat162(l2, l3);
}

// ---------------- HMMA bf16-split GEMM ----------------------------------------
// Y = X @ W^T + bias via XhWh + XhWl + XlWh (fp32 accum).
// CTA 128x128, 8 warps (4M x 2N), warp tile 32x64, k-step 32, cp.async 2-stage.
// Smem row stride 80B (64B data + 16B pad) -> ldmatrix conflict-free.
#define GT_TILE  (128 * 80)          // 10240 B per tile
#define GT_STAGE (4 * GT_TILE)       // Ah, Al, Bh, Bl
#define GSMEM    (2 * GT_STAGE)      // 81920 B

template <int MODE>
__global__ void __launch_bounds__(256)
gemm_mma(const float* __restrict__ bias, float* __restrict__ Yout)
{
    extern __shared__ char smem[];
    const uint32_t sb = smem_u32(smem);

    const int tid  = threadIdx.x;
    const int lane = tid & 31;
    const int wid  = tid >> 5;
    const int wm   = wid & 3;          // 4 M-groups of 32 rows
    const int wn   = wid >> 2;         // 2 N-groups of 64 cols
    const int bm   = blockIdx.y << 7;
    const int bn   = blockIdx.x << 7;

    float acc[2][8][4];
#pragma unroll
    for (int mt = 0; mt < 2; mt++)
#pragma unroll
        for (int nt = 0; nt < 8; nt++)
#pragma unroll
            for (int e = 0; e < 4; e++) acc[mt][nt][e] = 0.0f;

    // per-thread gmem->smem chunk coords (2 x 16B per tile per k-step)
    const int r0 = tid >> 2, kg0 = tid & 3;                 // chunk 0
    const int r1 = (tid + 256) >> 2, kg1 = (tid + 256) & 3; // chunk 1

    const char* pxh = (const char*)g_xh;
    const char* pxl = (const char*)g_xl;
    const char* pwh = (const char*)g_wh;
    const char* pwl = (const char*)g_wl;

#define ISSUE(ks, st) do {                                                      \
    const uint32_t ss = sb + (st) * GT_STAGE;                                   \
    size_t ga0 = ((size_t)(bm + r0) * DM + (ks) * 32 + kg0 * 8) * 2;            \
    size_t gb0 = ((size_t)(bn + r0) * DM + (ks) * 32 + kg0 * 8) * 2;            \
    size_t ga1 = ((size_t)(bm + r1) * DM + (ks) * 32 + kg1 * 8) * 2;            \
    size_t gb1 = ((size_t)(bn + r1) * DM + (ks) * 32 + kg1 * 8) * 2;            \
    uint32_t s0 = r0 * 80 + kg0 * 16, s1 = r1 * 80 + kg1 * 16;                  \
    cpa16(ss + 0 * GT_TILE + s0, pxh + ga0);                                    \
    cpa16(ss + 1 * GT_TILE + s0, pxl + ga0);                                    \
    cpa16(ss + 2 * GT_TILE + s0, pwh + gb0);                                    \
    cpa16(ss + 3 * GT_TILE + s0, pwl + gb0);                                    \
    cpa16(ss + 0 * GT_TILE + s1, pxh + ga1);                                    \
    cpa16(ss + 1 * GT_TILE + s1, pxl + ga1);                                    \
    cpa16(ss + 2 * GT_TILE + s1, pwh + gb1);                                    \
    cpa16(ss + 3 * GT_TILE + s1, pwl + gb1);                                    \
    asm volatile("cp.async.commit_group;" ::: "memory");                        \
} while (0)

    ISSUE(0, 0);

    const int lrow = lane & 7;
    const int sel  = lane >> 3;    // 0..3: (m8 half, k8 half)
    const uint32_t fr_off = ((sel & 1) * 8 + lrow) * 80 + (sel >> 1) * 16;

    for (int ks = 0; ks < 32; ks++) {
        const int st = ks & 1;
        if (ks + 1 < 32) {
            ISSUE(ks + 1, st ^ 1);
            asm volatile("cp.async.wait_group 1;" ::: "memory");
        } else {
            asm volatile("cp.async.wait_group 0;" ::: "memory");
        }
        __syncthreads();

        const uint32_t sAh = sb + st * GT_STAGE;
        const uint32_t sAl = sAh + GT_TILE;
        const uint32_t sBh = sAh + 2 * GT_TILE;
        const uint32_t sBl = sAh + 3 * GT_TILE;

#pragma unroll
        for (int k16 = 0; k16 < 2; k16++) {
            const uint32_t ko = fr_off + k16 * 32;   // k16*2 granules of 16B
            uint32_t ah[2][4], al[2][4], bh[4][4], bl[4][4];
#pragma unroll
            for (int mt = 0; mt < 2; mt++) {
                uint32_t base = (uint32_t)(wm * 32 + mt * 16) * 80 + ko;
                ldsm4(ah[mt], sAh + base);
                ldsm4(al[mt], sAl + base);
            }
#pragma unroll
            for (int nq = 0; nq < 4; nq++) {
                uint32_t base = (uint32_t)(wn * 64 + nq * 16) * 80 + ko;
                ldsm4(bh[nq], sBh + base);
                ldsm4(bl[nq], sBl + base);
            }
#pragma unroll
            for (int mt = 0; mt < 2; mt++)
#pragma unroll
                for (int nt = 0; nt < 8; nt++) {
                    const int nq = nt >> 1, o = nt & 1;
                    mma_bf16(acc[mt][nt], ah[mt], bh[nq][o], bh[nq][o + 2]);
                    mma_bf16(acc[mt][nt], ah[mt], bl[nq][o], bl[nq][o + 2]);
                    mma_bf16(acc[mt][nt], al[mt], bh[nq][o], bh[nq][o + 2]);
                }
        }
        __syncthreads();
    }
#undef ISSUE

    // ---- epilogue ----
    const int gid = lane >> 2;
    const int t4  = lane & 3;
#pragma unroll
    for (int mt = 0; mt < 2; mt++) {
#pragma unroll
        for (int nt = 0; nt < 8; nt++) {
            const int n0 = bn + wn * 64 + nt * 8 + t4 * 2;
            const float b0 = bias[n0], b1 = bias[n0 + 1];
#pragma unroll
            for (int half = 0; half < 2; half++) {
                const int m = bm + wm * 32 + mt * 16 + gid + half * 8;
                float2 val;
                val.x = acc[mt][nt][half * 2 + 0] + b0;
                val.y = acc[mt][nt][half * 2 + 1] + b1;
                if (MODE <= 2) {
                    const int bb = m >> 11;
                    const int s  = m & (S_LEN - 1);
                    const int h  = n0 >> 6;
                    const int d  = n0 & 63;
                    float* dstp = (MODE == 0) ? g_q : (MODE == 1) ? g_k : g_v;
                    *(float2*)(dstp + (((size_t)(bb * NH + h) * S_LEN) + s) * DKH + d) = val;
                } else {
                    *(float2*)(Yout + (size_t)m * DM + n0) = val;
                }
            }
        }
    }
}

// ---------------- flash attention (R1 fp32, known-good 918us) -----------------
__global__ void __launch_bounds__(256)
attn_fwd()
{
    __shared__ float Qs[64 * 64];
    __shared__ float KPs[64 * 64];
    __shared__ float Vs[64 * 64];

    const int tid = threadIdx.x;
    const int tx  = tid & 15;
    const int ty  = tid >> 4;
    const int bh  = blockIdx.y;
    const int q0  = blockIdx.x << 6;

    const float* Qb = g_q + (size_t)bh * S_LEN * DKH;
    const float* Kb = g_k + (size_t)bh * S_LEN * DKH;
    const float* Vb = g_v + (size_t)bh * S_LEN * DKH;

    const int swr = (ty & 7) << 2;
    const int swc = (tx & 7) << 2;

#pragma unroll
    for (int p = 0; p < 4; p++) {
        int idx = tid + (p << 8);
        int r   = idx >> 4;
        int c4  = (idx & 15) << 2;
        int sw  = ((r >> 2) & 7) << 2;
        float4 qv = *(const float4*)(Qb + (size_t)(q0 + r) * DKH + c4);
        *(float4*)&Qs[(r << 6) + (c4 ^ sw)] = qv;
    }

    float m_r[4], l_r[4], o_acc[4][4];
#pragma unroll
    for (int i = 0; i < 4; i++) {
        m_r[i] = -1e30f; l_r[i] = 0.0f;
#pragma unroll
        for (int j = 0; j < 4; j++) o_acc[i][j] = 0.0f;
    }
    __syncthreads();

    for (int kt = 0; kt < S_LEN; kt += 64) {
#pragma unroll
        for (int p = 0; p < 4; p++) {
            int idx = tid + (p << 8);
            int r   = idx >> 4;
            int c4  = (idx & 15) << 2;
            int sw  = ((r >> 2) & 7) << 2;
            float4 kv = *(const float4*)(Kb + (size_t)(kt + r) * DKH + c4);
            float4 vv = *(const float4*)(Vb + (size_t)(kt + r) * DKH + c4);
            *(float4*)&KPs[(r << 6) + (c4 ^ sw)] = kv;
            *(float4*)&Vs[(r << 6) + c4]         = vv;
        }
        __syncthreads();

        float sacc[4][4];
#pragma unroll
        for (int i = 0; i < 4; i++)
#pragma unroll
            for (int j = 0; j < 4; j++) sacc[i][j] = 0.0f;

#pragma unroll 8
        for (int d0 = 0; d0 < 64; d0 += 4) {
            float4 aq[4], bk[4];
#pragma unroll
            for (int i = 0; i < 4; i++)
                aq[i] = *(const float4*)&Qs[(((ty << 2) + i) << 6) + (d0 ^ swr)];
#pragma unroll
            for (int j = 0; j < 4; j++)
                bk[j] = *(const float4*)&KPs[(((tx << 2) + j) << 6) + (d0 ^ swc)];
#pragma unroll
            for (int i = 0; i < 4; i++) {
                const float* ai = &aq[i].x;
#pragma unroll
                for (int j = 0; j < 4; j++) {
                    const float* bj = &bk[j].x;
                    float s = sacc[i][j];
                    s = fmaf(ai[0], bj[0], s);
                    s = fmaf(ai[1], bj[1], s);
                    s = fmaf(ai[2], bj[2], s);
                    s = fmaf(ai[3], bj[3], s);
                    sacc[i][j] = s;
                }
            }
        }

        float4 pst[4];
#pragma unroll
        for (int i = 0; i < 4; i++) {
            float s0 = sacc[i][0] * 0.125f;
            float s1 = sacc[i][1] * 0.125f;
            float s2 = sacc[i][2] * 0.125f;
            float s3 = sacc[i][3] * 0.125f;
            float mx = fmaxf(fmaxf(s0, s1), fmaxf(s2, s3));
#pragma unroll
            for (int off = 8; off >= 1; off >>= 1)
                mx = fmaxf(mx, __shfl_xor_sync(0xffffffffu, mx, off));
            float newm = fmaxf(m_r[i], mx);
            float p0 = __expf(s0 - newm);
            float p1 = __expf(s1 - newm);
            float p2 = __expf(s2 - newm);
            float p3 = __expf(s3 - newm);
            float rs = (p0 + p1) + (p2 + p3);
#pragma unroll
            for (int off = 8; off >= 1; off >>= 1)
                rs += __shfl_xor_sync(0xffffffffu, rs, off);
            float corr = __expf(m_r[i] - newm);
            l_r[i] = l_r[i] * corr + rs;
            m_r[i] = newm;
#pragma unroll
            for (int j = 0; j < 4; j++) o_acc[i][j] *= corr;
            pst[i] = make_float4(p0, p1, p2, p3);
        }

        __syncthreads();
#pragma unroll
        for (int i = 0; i < 4; i++)
            *(float4*)&KPs[(((ty << 2) + i) << 6) + ((tx << 2) ^ swr)] = pst[i];
        __syncthreads();

#pragma unroll 8
        for (int c0 = 0; c0 < 64; c0 += 4) {
            float4 ap[4], vv4[4];
#pragma unroll
            for (int i = 0; i < 4; i++)
                ap[i] = *(const float4*)&KPs[(((ty << 2) + i) << 6) + (c0 ^ swr)];
#pragma unroll
            for (int t = 0; t < 4; t++)
                vv4[t] = *(const float4*)&Vs[((c0 + t) << 6) + (tx << 2)];
#pragma unroll
            for (int i = 0; i < 4; i++) {
                const float* pi = &ap[i].x;
#pragma unroll
                for (int j = 0; j < 4; j++) {
                    float o = o_acc[i][j];
                    o = fmaf(pi[0], (&vv4[0].x)[j], o);
                    o = fmaf(pi[1], (&vv4[1].x)[j], o);
                    o = fmaf(pi[2], (&vv4[2].x)[j], o);
                    o = fmaf(pi[3], (&vv4[3].x)[j], o);
                    o_acc[i][j] = o;
                }
            }
        }
        __syncthreads();
    }

    const int b = bh >> 4;
    const int h = bh & 15;
#pragma unroll
    for (int i = 0; i < 4; i++) {
        float inv  = 1.0f / l_r[i];
        int   srow = q0 + (ty << 2) + i;
        float4 ov = make_float4(o_acc[i][0] * inv, o_acc[i][1] * inv,
                                o_acc[i][2] * inv, o_acc[i][3] * inv);
        *(float4*)(g_ao + ((size_t)(b * S_LEN + srow)) * DM + (h << 6) + (tx << 2)) = ov;
    }
}

// ---------------------------------------------------------------------------
extern "C" void kernel_launch(void* const* d_in, const int* in_sizes, int n_in,
                              void* d_out, int out_size)
{
    const float* q  = (const float*)d_in[0];
    const float* k  = (const float*)d_in[1];
    const float* v  = (const float*)d_in[2];
    const float* wq = (const float*)d_in[3];
    const float* bq = (const float*)d_in[4];
    const float* wk = (const float*)d_in[5];
    const float* bk = (const float*)d_in[6];
    const float* wv = (const float*)d_in[7];
    const float* bv = (const float*)d_in[8];
    const float* wo = (const float*)d_in[9];
    const float* bo = (const float*)d_in[10];
    float* out = (float*)d_out;

    cudaFuncSetAttribute(gemm_mma<0>, cudaFuncAttributeMaxDynamicSharedMemorySize, GSMEM);
    cudaFuncSetAttribute(gemm_mma<1>, cudaFuncAttributeMaxDynamicSharedMemorySize, GSMEM);
    cudaFuncSetAttribute(gemm_mma<2>, cudaFuncAttributeMaxDynamicSharedMemorySize, GSMEM);
    cudaFuncSetAttribute(gemm_mma<3>, cudaFuncAttributeMaxDynamicSharedMemorySize, GSMEM);

    const int n4x = M_ROWS * DM / 4;
    const int n4w = DM * DM / 4;
    dim3 gg(DM / 128, M_ROWS / 128);   // (8, 32)

    conv_split<0, 0><<<n4x / 256, 256>>>((const float4*)q, n4x);
    conv_split<1, 0><<<n4w / 256, 256>>>((const float4*)wq, n4w);
    gemm_mma<0><<<gg, 256, GSMEM>>>(bq, nullptr);

    conv_split<0, 0><<<n4x / 256, 256>>>((const float4*)k, n4x);
    conv_split<1, 0><<<n4w / 256, 256>>>((const float4*)wk, n4w);
    gemm_mma<1><<<gg, 256, GSMEM>>>(bk, nullptr);

    conv_split<0, 0><<<n4x / 256, 256>>>((const float4*)v, n4x);
    conv_split<1, 0><<<n4w / 256, 256>>>((const float4*)wv, n4w);
    gemm_mma<2><<<gg, 256, GSMEM>>>(bv, nullptr);

    attn_fwd<<<dim3(S_LEN / 64, B_SZ * NH), 256>>>();

    conv_split<0, 1><<<n4x / 256, 256>>>(nullptr, n4x);
    conv_split<1, 0><<<n4w / 256, 256>>>((const float4*)wo, n4w);
    gemm_mma<3><<<gg, 256, GSMEM>>>(bo, out);
}

// round 6
// speedup vs baseline: 2.3629x; 1.6368x over previous
#include <cuda_runtime.h>
#include <cuda_bf16.h>
#include <cstdint>

#define B_SZ   2
#define S_LEN  2048
#define DM     1024
#define NH     16
#define DKH    64
#define M_ROWS (B_SZ * S_LEN)   // 4096

// ---------------- scratch ----------------------------------------------------
__device__ __align__(16) float g_ao[(size_t)M_ROWS * DM];
// bf16 hi/lo split buffers for GEMM inputs
__device__ __align__(16) __nv_bfloat16 g_xh[(size_t)M_ROWS * DM];
__device__ __align__(16) __nv_bfloat16 g_xl[(size_t)M_ROWS * DM];
__device__ __align__(16) __nv_bfloat16 g_wh[(size_t)DM * DM];
__device__ __align__(16) __nv_bfloat16 g_wl[(size_t)DM * DM];
// bf16 hi/lo split-head Q/K/V [B*H, S, 64]  (Q pre-scaled by 0.125*log2e)
__device__ __align__(16) __nv_bfloat16 g_qh[(size_t)B_SZ * NH * S_LEN * DKH];
__device__ __align__(16) __nv_bfloat16 g_ql[(size_t)B_SZ * NH * S_LEN * DKH];
__device__ __align__(16) __nv_bfloat16 g_kh[(size_t)B_SZ * NH * S_LEN * DKH];
__device__ __align__(16) __nv_bfloat16 g_kl[(size_t)B_SZ * NH * S_LEN * DKH];
__device__ __align__(16) __nv_bfloat16 g_vh[(size_t)B_SZ * NH * S_LEN * DKH];
__device__ __align__(16) __nv_bfloat16 g_vl[(size_t)B_SZ * NH * S_LEN * DKH];

// ---------------- helpers -----------------------------------------------------
__device__ __forceinline__ uint32_t smem_u32(const void* p) {
    uint32_t a;
    asm("{ .reg .u64 t; cvta.to.shared.u64 t, %1; cvt.u32.u64 %0, t; }"
        : "=r"(a) : "l"(p));
    return a;
}
__device__ __forceinline__ void cpa16(uint32_t s, const void* g) {
    asm volatile("cp.async.cg.shared.global [%0], [%1], 16;" :: "r"(s), "l"(g) : "memory");
}
__device__ __forceinline__ void ldsm4(uint32_t r[4], uint32_t addr) {
    asm volatile("ldmatrix.sync.aligned.m8n8.x4.shared.b16 {%0,%1,%2,%3}, [%4];"
                 : "=r"(r[0]), "=r"(r[1]), "=r"(r[2]), "=r"(r[3]) : "r"(addr));
}
__device__ __forceinline__ void ldsm4t(uint32_t r[4], uint32_t addr) {
    asm volatile("ldmatrix.sync.aligned.m8n8.x4.trans.shared.b16 {%0,%1,%2,%3}, [%4];"
                 : "=r"(r[0]), "=r"(r[1]), "=r"(r[2]), "=r"(r[3]) : "r"(addr));
}
__device__ __forceinline__ void mma_bf16(float d[4], const uint32_t a[4],
                                         uint32_t b0, uint32_t b1) {
    asm volatile(
        "mma.sync.aligned.m16n8k16.row.col.f32.bf16.bf16.f32 "
        "{%0,%1,%2,%3},{%4,%5,%6,%7},{%8,%9},{%0,%1,%2,%3};"
        : "+f"(d[0]), "+f"(d[1]), "+f"(d[2]), "+f"(d[3])
        : "r"(a[0]), "r"(a[1]), "r"(a[2]), "r"(a[3]), "r"(b0), "r"(b1));
}
__device__ __forceinline__ float ex2(float x) {
    float y; asm("ex2.approx.ftz.f32 %0, %1;" : "=f"(y) : "f"(x)); return y;
}

// ---------------- fp32 -> bf16 hi/lo split (GEMM inputs) ----------------------
template <int DST, int SRC_AO>
__global__ void __launch_bounds__(256)
conv_split(const float4* __restrict__ x, int n4)
{
    if (SRC_AO) x = (const float4*)g_ao;
    __nv_bfloat162* hi = (DST == 0) ? (__nv_bfloat162*)g_xh : (__nv_bfloat162*)g_wh;
    __nv_bfloat162* lo = (DST == 0) ? (__nv_bfloat162*)g_xl : (__nv_bfloat162*)g_wl;
    int i = blockIdx.x * 256 + threadIdx.x;
    if (i >= n4) return;
    float4 v = x[i];
    __nv_bfloat16 h0 = __float2bfloat16(v.x);
    __nv_bfloat16 h1 = __float2bfloat16(v.y);
    __nv_bfloat16 h2 = __float2bfloat16(v.z);
    __nv_bfloat16 h3 = __float2bfloat16(v.w);
    __nv_bfloat16 l0 = __float2bfloat16(v.x - __bfloat162float(h0));
    __nv_bfloat16 l1 = __float2bfloat16(v.y - __bfloat162float(h1));
    __nv_bfloat16 l2 = __float2bfloat16(v.z - __bfloat162float(h2));
    __nv_bfloat16 l3 = __float2bfloat16(v.w - __bfloat162float(h3));
    hi[i * 2 + 0] = __nv_bfloat162(h0, h1);
    hi[i * 2 + 1] = __nv_bfloat162(h2, h3);
    lo[i * 2 + 0] = __nv_bfloat162(l0, l1);
    lo[i * 2 + 1] = __nv_bfloat162(l2, l3);
}

// ---------------- HMMA bf16-split GEMM ----------------------------------------
// Y = X @ W^T + bias via XhWh + XhWl + XlWh (fp32 accum).
// MODE 0/1/2: write split-head bf16 hi/lo Q/K/V (Q pre-scaled for exp2 softmax).
// MODE 3: write fp32 row-major out.
#define GT_TILE  (128 * 80)
#define GT_STAGE (4 * GT_TILE)
#define GSMEM    (2 * GT_STAGE)

template <int MODE>
__global__ void __launch_bounds__(256)
gemm_mma(const float* __restrict__ bias, float* __restrict__ Yout)
{
    extern __shared__ char smem[];
    const uint32_t sb = smem_u32(smem);

    const int tid  = threadIdx.x;
    const int lane = tid & 31;
    const int wid  = tid >> 5;
    const int wm   = wid & 3;
    const int wn   = wid >> 2;
    const int bm   = blockIdx.y << 7;
    const int bn   = blockIdx.x << 7;

    float acc[2][8][4];
#pragma unroll
    for (int mt = 0; mt < 2; mt++)
#pragma unroll
        for (int nt = 0; nt < 8; nt++)
#pragma unroll
            for (int e = 0; e < 4; e++) acc[mt][nt][e] = 0.0f;

    const int r0 = tid >> 2, kg0 = tid & 3;
    const int r1 = (tid + 256) >> 2, kg1 = (tid + 256) & 3;

    const char* pxh = (const char*)g_xh;
    const char* pxl = (const char*)g_xl;
    const char* pwh = (const char*)g_wh;
    const char* pwl = (const char*)g_wl;

#define ISSUE(ks, st) do {                                                      \
    const uint32_t ss = sb + (st) * GT_STAGE;                                   \
    size_t ga0 = ((size_t)(bm + r0) * DM + (ks) * 32 + kg0 * 8) * 2;            \
    size_t gb0 = ((size_t)(bn + r0) * DM + (ks) * 32 + kg0 * 8) * 2;            \
    size_t ga1 = ((size_t)(bm + r1) * DM + (ks) * 32 + kg1 * 8) * 2;            \
    size_t gb1 = ((size_t)(bn + r1) * DM + (ks) * 32 + kg1 * 8) * 2;            \
    uint32_t s0 = r0 * 80 + kg0 * 16, s1 = r1 * 80 + kg1 * 16;                  \
    cpa16(ss + 0 * GT_TILE + s0, pxh + ga0);                                    \
    cpa16(ss + 1 * GT_TILE + s0, pxl + ga0);                                    \
    cpa16(ss + 2 * GT_TILE + s0, pwh + gb0);                                    \
    cpa16(ss + 3 * GT_TILE + s0, pwl + gb0);                                    \
    cpa16(ss + 0 * GT_TILE + s1, pxh + ga1);                                    \
    cpa16(ss + 1 * GT_TILE + s1, pxl + ga1);                                    \
    cpa16(ss + 2 * GT_TILE + s1, pwh + gb1);                                    \
    cpa16(ss + 3 * GT_TILE + s1, pwl + gb1);                                    \
    asm volatile("cp.async.commit_group;" ::: "memory");                        \
} while (0)

    ISSUE(0, 0);

    const int lrow = lane & 7;
    const int sel  = lane >> 3;
    const uint32_t fr_off = ((sel & 1) * 8 + lrow) * 80 + (sel >> 1) * 16;

    for (int ks = 0; ks < 32; ks++) {
        const int st = ks & 1;
        if (ks + 1 < 32) {
            ISSUE(ks + 1, st ^ 1);
            asm volatile("cp.async.wait_group 1;" ::: "memory");
        } else {
            asm volatile("cp.async.wait_group 0;" ::: "memory");
        }
        __syncthreads();

        const uint32_t sAh = sb + st * GT_STAGE;
        const uint32_t sAl = sAh + GT_TILE;
        const uint32_t sBh = sAh + 2 * GT_TILE;
        const uint32_t sBl = sAh + 3 * GT_TILE;

#pragma unroll
        for (int k16 = 0; k16 < 2; k16++) {
            const uint32_t ko = fr_off + k16 * 32;
            uint32_t ah[2][4], al[2][4], bh[4][4], bl[4][4];
#pragma unroll
            for (int mt = 0; mt < 2; mt++) {
                uint32_t base = (uint32_t)(wm * 32 + mt * 16) * 80 + ko;
                ldsm4(ah[mt], sAh + base);
                ldsm4(al[mt], sAl + base);
            }
#pragma unroll
            for (int nq = 0; nq < 4; nq++) {
                uint32_t base = (uint32_t)(wn * 64 + nq * 16) * 80 + ko;
                ldsm4(bh[nq], sBh + base);
                ldsm4(bl[nq], sBl + base);
            }
#pragma unroll
            for (int mt = 0; mt < 2; mt++)
#pragma unroll
                for (int nt = 0; nt < 8; nt++) {
                    const int nq = nt >> 1, o = nt & 1;
                    mma_bf16(acc[mt][nt], ah[mt], bh[nq][o], bh[nq][o + 2]);
                    mma_bf16(acc[mt][nt], ah[mt], bl[nq][o], bl[nq][o + 2]);
                    mma_bf16(acc[mt][nt], al[mt], bh[nq][o], bh[nq][o + 2]);
                }
        }
        __syncthreads();
    }
#undef ISSUE

    // ---- epilogue ----
    const int gid = lane >> 2;
    const int t4  = lane & 3;
    const float qscale = 0.18033688011112042f;   // 0.125 * log2(e)
#pragma unroll
    for (int mt = 0; mt < 2; mt++) {
#pragma unroll
        for (int nt = 0; nt < 8; nt++) {
            const int n0 = bn + wn * 64 + nt * 8 + t4 * 2;
            const float b0 = bias[n0], b1 = bias[n0 + 1];
#pragma unroll
            for (int half = 0; half < 2; half++) {
                const int m = bm + wm * 32 + mt * 16 + gid + half * 8;
                float vx = acc[mt][nt][half * 2 + 0] + b0;
                float vy = acc[mt][nt][half * 2 + 1] + b1;
                if (MODE <= 2) {
                    if (MODE == 0) { vx *= qscale; vy *= qscale; }
                    const int bb = m >> 11;
                    const int s  = m & (S_LEN - 1);
                    const int h  = n0 >> 6;
                    const int d  = n0 & 63;
                    __nv_bfloat16 hx = __float2bfloat16(vx);
                    __nv_bfloat16 hy = __float2bfloat16(vy);
                    __nv_bfloat16 lx = __float2bfloat16(vx - __bfloat162float(hx));
                    __nv_bfloat16 ly = __float2bfloat16(vy - __bfloat162float(hy));
                    size_t off = (((size_t)(bb * NH + h) * S_LEN) + s) * DKH + d;
                    __nv_bfloat16 *ph, *pl;
                    if (MODE == 0)      { ph = g_qh; pl = g_ql; }
                    else if (MODE == 1) { ph = g_kh; pl = g_kl; }
                    else                { ph = g_vh; pl = g_vl; }
                    *(__nv_bfloat162*)(ph + off) = __nv_bfloat162(hx, hy);
                    *(__nv_bfloat162*)(pl + off) = __nv_bfloat162(lx, ly);
                } else {
                    float2 val; val.x = vx; val.y = vy;
                    *(float2*)(Yout + (size_t)m * DM + n0) = val;
                }
            }
        }
    }
}

// ---------------- HMMA flash attention ----------------------------------------
// CTA = (bh, 128 q rows). 8 warps x 16 rows. KV tiles of 128.
// QK^T and P.V both via 3-term bf16 hi/lo split. exp2-domain online softmax.
#define AT_S   144                 // QKV tile row stride (bytes)
#define AT_PS  272                 // P tile row stride (bytes)
#define AT_TSZ (128 * AT_S)        // 18432
#define AT_PSZ (128 * AT_PS)       // 34816
#define oQh 0
#define oQl (1 * AT_TSZ)
#define oKh (2 * AT_TSZ)
#define oKl (3 * AT_TSZ)
#define oVh (4 * AT_TSZ)
#define oVl (5 * AT_TSZ)
#define oPh (6 * AT_TSZ)
#define oPl (6 * AT_TSZ + AT_PSZ)
#define ASMEM (6 * AT_TSZ + 2 * AT_PSZ)   // 180224

__global__ void __launch_bounds__(256, 1)
attn_mma()
{
    extern __shared__ char sm[];
    const uint32_t sb = smem_u32(sm);

    const int tid  = threadIdx.x;
    const int lane = tid & 31;
    const int w    = tid >> 5;
    const int gid  = lane >> 2;
    const int t4   = lane & 3;
    const int lrow = lane & 7;
    const int sel  = lane >> 3;
    const int bh   = blockIdx.y;
    const int q0   = blockIdx.x << 7;

    const size_t hb = (size_t)bh * S_LEN * DKH;
    const __nv_bfloat16* gqh = g_qh + hb;
    const __nv_bfloat16* gql = g_ql + hb;
    const __nv_bfloat16* gkh = g_kh + hb;
    const __nv_bfloat16* gkl = g_kl + hb;
    const __nv_bfloat16* gvh = g_vh + hb;
    const __nv_bfloat16* gvl = g_vl + hb;

    // ---- load Q tile (hi/lo) ----
#pragma unroll
    for (int p = 0; p < 4; p++) {
        int idx = tid + (p << 8);
        int r = idx >> 3, g = idx & 7;
        uint32_t so = r * AT_S + g * 16;
        size_t ge = (size_t)(q0 + r) * DKH + g * 8;
        *(uint4*)(sm + oQh + so) = *(const uint4*)(gqh + ge);
        *(uint4*)(sm + oQl + so) = *(const uint4*)(gql + ge);
    }
    __syncthreads();

    // resident Q fragments (A operand), 4 k16 steps
    const uint32_t frq = (uint32_t)((sel & 1) * 8 + lrow) * AT_S + (sel >> 1) * 16;
    uint32_t qfh[4][4], qfl[4][4];
#pragma unroll
    for (int k16 = 0; k16 < 4; k16++) {
        uint32_t a = sb + (uint32_t)(w * 16) * AT_S + frq + k16 * 32;
        ldsm4(qfh[k16], a + oQh);
        ldsm4(qfl[k16], a + oQl);
    }

    float m0 = -1e30f, m1 = -1e30f, l0 = 0.0f, l1 = 0.0f;
    float oacc[8][4];
#pragma unroll
    for (int nt = 0; nt < 8; nt++)
#pragma unroll
        for (int e = 0; e < 4; e++) oacc[nt][e] = 0.0f;

    for (int kt = 0; kt < S_LEN; kt += 128) {
        __syncthreads();   // previous iter done with K/V
        // ---- load K/V tiles (hi/lo) ----
#pragma unroll
        for (int p = 0; p < 4; p++) {
            int idx = tid + (p << 8);
            int r = idx >> 3, g = idx & 7;
            uint32_t so = r * AT_S + g * 16;
            size_t ge = (size_t)(kt + r) * DKH + g * 8;
            *(uint4*)(sm + oKh + so) = *(const uint4*)(gkh + ge);
            *(uint4*)(sm + oKl + so) = *(const uint4*)(gkl + ge);
            *(uint4*)(sm + oVh + so) = *(const uint4*)(gvh + ge);
            *(uint4*)(sm + oVl + so) = *(const uint4*)(gvl + ge);
        }
        __syncthreads();

        // ---- S = Q K^T  (3-term split) ----
        float sacc[16][4];
#pragma unroll
        for (int nt = 0; nt < 16; nt++)
#pragma unroll
            for (int e = 0; e < 4; e++) sacc[nt][e] = 0.0f;

#pragma unroll
        for (int k16 = 0; k16 < 4; k16++) {
#pragma unroll
            for (int nb = 0; nb < 8; nb++) {
                uint32_t kbh[4], kbl[4];
                uint32_t off = sb + (uint32_t)(nb * 16) * AT_S + frq + k16 * 32;
                ldsm4(kbh, off + oKh);
                ldsm4(kbl, off + oKl);
                mma_bf16(sacc[nb * 2 + 0], qfh[k16], kbh[0], kbh[2]);
                mma_bf16(sacc[nb * 2 + 0], qfh[k16], kbl[0], kbl[2]);
                mma_bf16(sacc[nb * 2 + 0], qfl[k16], kbh[0], kbh[2]);
                mma_bf16(sacc[nb * 2 + 1], qfh[k16], kbh[1], kbh[3]);
                mma_bf16(sacc[nb * 2 + 1], qfh[k16], kbl[1], kbl[3]);
                mma_bf16(sacc[nb * 2 + 1], qfl[k16], kbh[1], kbh[3]);
            }
        }

        // ---- online softmax (exp2 domain, intra-warp reductions) ----
        float mx0 = -1e30f, mx1 = -1e30f;
#pragma unroll
        for (int nt = 0; nt < 16; nt++) {
            mx0 = fmaxf(mx0, fmaxf(sacc[nt][0], sacc[nt][1]));
            mx1 = fmaxf(mx1, fmaxf(sacc[nt][2], sacc[nt][3]));
        }
        mx0 = fmaxf(mx0, __shfl_xor_sync(0xffffffffu, mx0, 1));
        mx0 = fmaxf(mx0, __shfl_xor_sync(0xffffffffu, mx0, 2));
        mx1 = fmaxf(mx1, __shfl_xor_sync(0xffffffffu, mx1, 1));
        mx1 = fmaxf(mx1, __shfl_xor_sync(0xffffffffu, mx1, 2));
        const float nm0 = fmaxf(m0, mx0);
        const float nm1 = fmaxf(m1, mx1);

        float rs0 = 0.0f, rs1 = 0.0f;
#pragma unroll
        for (int nt = 0; nt < 16; nt++) {
            sacc[nt][0] = ex2(sacc[nt][0] - nm0);
            sacc[nt][1] = ex2(sacc[nt][1] - nm0);
            sacc[nt][2] = ex2(sacc[nt][2] - nm1);
            sacc[nt][3] = ex2(sacc[nt][3] - nm1);
            rs0 += sacc[nt][0] + sacc[nt][1];
            rs1 += sacc[nt][2] + sacc[nt][3];
        }
        rs0 += __shfl_xor_sync(0xffffffffu, rs0, 1);
        rs0 += __shfl_xor_sync(0xffffffffu, rs0, 2);
        rs1 += __shfl_xor_sync(0xffffffffu, rs1, 1);
        rs1 += __shfl_xor_sync(0xffffffffu, rs1, 2);

        const float c0 = ex2(m0 - nm0);
        const float c1 = ex2(m1 - nm1);
        l0 = l0 * c0 + rs0;  m0 = nm0;
        l1 = l1 * c1 + rs1;  m1 = nm1;
#pragma unroll
        for (int nt = 0; nt < 8; nt++) {
            oacc[nt][0] *= c0; oacc[nt][1] *= c0;
            oacc[nt][2] *= c1; oacc[nt][3] *= c1;
        }

        // ---- store P (hi/lo bf16) to per-warp smem rows ----
        const uint32_t pr0 = (uint32_t)(w * 16 + gid) * AT_PS + t4 * 4;
        const uint32_t pr1 = pr0 + 8 * AT_PS;
#pragma unroll
        for (int nt = 0; nt < 16; nt++) {
            const uint32_t co = nt * 16;
            float p0 = sacc[nt][0], p1 = sacc[nt][1];
            float p2 = sacc[nt][2], p3 = sacc[nt][3];
            __nv_bfloat16 h0 = __float2bfloat16(p0), h1 = __float2bfloat16(p1);
            __nv_bfloat16 h2 = __float2bfloat16(p2), h3 = __float2bfloat16(p3);
            __nv_bfloat16 e0 = __float2bfloat16(p0 - __bfloat162float(h0));
            __nv_bfloat16 e1 = __float2bfloat16(p1 - __bfloat162float(h1));
            __nv_bfloat16 e2 = __float2bfloat16(p2 - __bfloat162float(h2));
            __nv_bfloat16 e3 = __float2bfloat16(p3 - __bfloat162float(h3));
            *(__nv_bfloat162*)(sm + oPh + pr0 + co) = __nv_bfloat162(h0, h1);
            *(__nv_bfloat162*)(sm + oPl + pr0 + co) = __nv_bfloat162(e0, e1);
            *(__nv_bfloat162*)(sm + oPh + pr1 + co) = __nv_bfloat162(h2, h3);
            *(__nv_bfloat162*)(sm + oPl + pr1 + co) = __nv_bfloat162(e2, e3);
        }
        __syncwarp();   // P rows are warp-private

        // ---- O += P V  (3-term split; V via ldmatrix.trans) ----
        const uint32_t frp = (uint32_t)(w * 16 + (sel & 1) * 8 + lrow) * AT_PS + (sel >> 1) * 16;
#pragma unroll
        for (int k16 = 0; k16 < 8; k16++) {
            uint32_t afh[4], afl[4];
            uint32_t pa = sb + frp + k16 * 32;
            ldsm4(afh, pa + oPh);
            ldsm4(afl, pa + oPl);
            const uint32_t vrow = sb + (uint32_t)(k16 * 16 + (lane & 15)) * AT_S;
#pragma unroll
            for (int dg = 0; dg < 4; dg++) {
                uint32_t vbh[4], vbl[4];
                uint32_t va = vrow + (uint32_t)(dg * 2 + (lane >> 4)) * 16;
                ldsm4t(vbh, va + oVh);
                ldsm4t(vbl, va + oVl);
                mma_bf16(oacc[dg * 2 + 0], afh, vbh[0], vbh[1]);
                mma_bf16(oacc[dg * 2 + 0], afh, vbl[0], vbl[1]);
                mma_bf16(oacc[dg * 2 + 0], afl, vbh[0], vbh[1]);
                mma_bf16(oacc[dg * 2 + 1], afh, vbh[2], vbh[3]);
                mma_bf16(oacc[dg * 2 + 1], afh, vbl[2], vbl[3]);
                mma_bf16(oacc[dg * 2 + 1], afl, vbh[2], vbh[3]);
            }
        }
    }

    // ---- epilogue: normalize, write [B,S,H*64] fp32 into g_ao ----
    const int b = bh >> 4;
    const int h = bh & 15;
    const float inv0 = 1.0f / l0;
    const float inv1 = 1.0f / l1;
    const int r0 = q0 + w * 16 + gid;
    const int r1 = r0 + 8;
#pragma unroll
    for (int nt = 0; nt < 8; nt++) {
        const int col = (h << 6) + nt * 8 + t4 * 2;
        float2 v0, v1;
        v0.x = oacc[nt][0] * inv0; v0.y = oacc[nt][1] * inv0;
        v1.x = oacc[nt][2] * inv1; v1.y = oacc[nt][3] * inv1;
        *(float2*)(g_ao + (size_t)(b * S_LEN + r0) * DM + col) = v0;
        *(float2*)(g_ao + (size_t)(b * S_LEN + r1) * DM + col) = v1;
    }
}

// ---------------------------------------------------------------------------
extern "C" void kernel_launch(void* const* d_in, const int* in_sizes, int n_in,
                              void* d_out, int out_size)
{
    const float* q  = (const float*)d_in[0];
    const float* k  = (const float*)d_in[1];
    const float* v  = (const float*)d_in[2];
    const float* wq = (const float*)d_in[3];
    const float* bq = (const float*)d_in[4];
    const float* wk = (const float*)d_in[5];
    const float* bk = (const float*)d_in[6];
    const float* wv = (const float*)d_in[7];
    const float* bv = (const float*)d_in[8];
    const float* wo = (const float*)d_in[9];
    const float* bo = (const float*)d_in[10];
    float* out = (float*)d_out;

    cudaFuncSetAttribute(gemm_mma<0>, cudaFuncAttributeMaxDynamicSharedMemorySize, GSMEM);
    cudaFuncSetAttribute(gemm_mma<1>, cudaFuncAttributeMaxDynamicSharedMemorySize, GSMEM);
    cudaFuncSetAttribute(gemm_mma<2>, cudaFuncAttributeMaxDynamicSharedMemorySize, GSMEM);
    cudaFuncSetAttribute(gemm_mma<3>, cudaFuncAttributeMaxDynamicSharedMemorySize, GSMEM);
    cudaFuncSetAttribute(attn_mma,    cudaFuncAttributeMaxDynamicSharedMemorySize, ASMEM);

    const int n4x = M_ROWS * DM / 4;
    const int n4w = DM * DM / 4;
    dim3 gg(DM / 128, M_ROWS / 128);   // (8, 32)

    conv_split<0, 0><<<n4x / 256, 256>>>((const float4*)q, n4x);
    conv_split<1, 0><<<n4w / 256, 256>>>((const float4*)wq, n4w);
    gemm_mma<0><<<gg, 256, GSMEM>>>(bq, nullptr);

    conv_split<0, 0><<<n4x / 256, 256>>>((const float4*)k, n4x);
    conv_split<1, 0><<<n4w / 256, 256>>>((const float4*)wk, n4w);
    gemm_mma<1><<<gg, 256, GSMEM>>>(bk, nullptr);

    conv_split<0, 0><<<n4x / 256, 256>>>((const float4*)v, n4x);
    conv_split<1, 0><<<n4w / 256, 256>>>((const float4*)wv, n4w);
    gemm_mma<2><<<gg, 256, GSMEM>>>(bv, nullptr);

    attn_mma<<<dim3(S_LEN / 128, B_SZ * NH), 256, ASMEM>>>();

    conv_split<0, 1><<<n4x / 256, 256>>>(nullptr, n4x);
    conv_split<1, 0><<<n4w / 256, 256>>>((const float4*)wo, n4w);
    gemm_mma<3><<<gg, 256, GSMEM>>>(bo, out);
}

// round 7
// speedup vs baseline: 2.5099x; 1.0622x over previous
#include <cuda_runtime.h>
#include <cuda_bf16.h>
#include <cstdint>

#define B_SZ   2
#define S_LEN  2048
#define DM     1024
#define NH     16
#define DKH    64
#define M_ROWS (B_SZ * S_LEN)   // 4096
#define XELEMS ((size_t)M_ROWS * DM)
#define WELEMS ((size_t)DM * DM)

// ---------------- scratch ----------------------------------------------------
__device__ __align__(16) float g_ao[XELEMS];
// bf16 hi/lo split buffers: 3 slots (q/k/v inputs, q/k/v weights)
__device__ __align__(16) __nv_bfloat16 g_xh[3 * XELEMS];
__device__ __align__(16) __nv_bfloat16 g_xl[3 * XELEMS];
__device__ __align__(16) __nv_bfloat16 g_wh[3 * WELEMS];
__device__ __align__(16) __nv_bfloat16 g_wl[3 * WELEMS];
// bf16 hi/lo split-head Q/K/V [B*H, S, 64]  (Q pre-scaled by 0.125*log2e)
__device__ __align__(16) __nv_bfloat16 g_qh[(size_t)B_SZ * NH * S_LEN * DKH];
__device__ __align__(16) __nv_bfloat16 g_ql[(size_t)B_SZ * NH * S_LEN * DKH];
__device__ __align__(16) __nv_bfloat16 g_kh[(size_t)B_SZ * NH * S_LEN * DKH];
__device__ __align__(16) __nv_bfloat16 g_kl[(size_t)B_SZ * NH * S_LEN * DKH];
__device__ __align__(16) __nv_bfloat16 g_vh[(size_t)B_SZ * NH * S_LEN * DKH];
__device__ __align__(16) __nv_bfloat16 g_vl[(size_t)B_SZ * NH * S_LEN * DKH];

// ---------------- helpers -----------------------------------------------------
__device__ __forceinline__ uint32_t smem_u32(const void* p) {
    uint32_t a;
    asm("{ .reg .u64 t; cvta.to.shared.u64 t, %1; cvt.u32.u64 %0, t; }"
        : "=r"(a) : "l"(p));
    return a;
}
__device__ __forceinline__ void cpa16(uint32_t s, const void* g) {
    asm volatile("cp.async.cg.shared.global [%0], [%1], 16;" :: "r"(s), "l"(g) : "memory");
}
__device__ __forceinline__ void ldsm4(uint32_t r[4], uint32_t addr) {
    asm volatile("ldmatrix.sync.aligned.m8n8.x4.shared.b16 {%0,%1,%2,%3}, [%4];"
                 : "=r"(r[0]), "=r"(r[1]), "=r"(r[2]), "=r"(r[3]) : "r"(addr));
}
__device__ __forceinline__ void ldsm4t(uint32_t r[4], uint32_t addr) {
    asm volatile("ldmatrix.sync.aligned.m8n8.x4.trans.shared.b16 {%0,%1,%2,%3}, [%4];"
                 : "=r"(r[0]), "=r"(r[1]), "=r"(r[2]), "=r"(r[3]) : "r"(addr));
}
__device__ __forceinline__ void mma_bf16(float d[4], const uint32_t a[4],
                                         uint32_t b0, uint32_t b1) {
    asm volatile(
        "mma.sync.aligned.m16n8k16.row.col.f32.bf16.bf16.f32 "
        "{%0,%1,%2,%3},{%4,%5,%6,%7},{%8,%9},{%0,%1,%2,%3};"
        : "+f"(d[0]), "+f"(d[1]), "+f"(d[2]), "+f"(d[3])
        : "r"(a[0]), "r"(a[1]), "r"(a[2]), "r"(a[3]), "r"(b0), "r"(b1));
}
__device__ __forceinline__ float ex2(float x) {
    float y; asm("ex2.approx.ftz.f32 %0, %1;" : "=f"(y) : "f"(x)); return y;
}
__device__ __forceinline__ void split4(float4 v, __nv_bfloat162* hi, __nv_bfloat162* lo) {
    __nv_bfloat16 h0 = __float2bfloat16(v.x);
    __nv_bfloat16 h1 = __float2bfloat16(v.y);
    __nv_bfloat16 h2 = __float2bfloat16(v.z);
    __nv_bfloat16 h3 = __float2bfloat16(v.w);
    __nv_bfloat16 l0 = __float2bfloat16(v.x - __bfloat162float(h0));
    __nv_bfloat16 l1 = __float2bfloat16(v.y - __bfloat162float(h1));
    __nv_bfloat16 l2 = __float2bfloat16(v.z - __bfloat162float(h2));
    __nv_bfloat16 l3 = __float2bfloat16(v.w - __bfloat162float(h3));
    hi[0] = __nv_bfloat162(h0, h1); hi[1] = __nv_bfloat162(h2, h3);
    lo[0] = __nv_bfloat162(l0, l1); lo[1] = __nv_bfloat162(l2, l3);
}

// ---------------- fp32 -> bf16 hi/lo split kernels -----------------------------
__global__ void __launch_bounds__(256)
conv_x3(const float4* __restrict__ q, const float4* __restrict__ k,
        const float4* __restrict__ v)
{
    const int y = blockIdx.y;
    const float4* src = (y == 0) ? q : (y == 1) ? k : v;
    __nv_bfloat162* hi = (__nv_bfloat162*)(g_xh + (size_t)y * XELEMS);
    __nv_bfloat162* lo = (__nv_bfloat162*)(g_xl + (size_t)y * XELEMS);
    int i = blockIdx.x * 256 + threadIdx.x;
    split4(src[i], hi + i * 2, lo + i * 2);
}
__global__ void __launch_bounds__(256)
conv_w3(const float4* __restrict__ wq, const float4* __restrict__ wk,
        const float4* __restrict__ wv)
{
    const int y = blockIdx.y;
    const float4* src = (y == 0) ? wq : (y == 1) ? wk : wv;
    __nv_bfloat162* hi = (__nv_bfloat162*)(g_wh + (size_t)y * WELEMS);
    __nv_bfloat162* lo = (__nv_bfloat162*)(g_wl + (size_t)y * WELEMS);
    int i = blockIdx.x * 256 + threadIdx.x;
    split4(src[i], hi + i * 2, lo + i * 2);
}
// split g_ao -> slot 0 of x buffers / wo -> slot 0 of w buffers
__global__ void __launch_bounds__(256)
conv_ao_wo(const float4* __restrict__ wo)
{
    int i = blockIdx.x * 256 + threadIdx.x;
    const int n4w = (int)(WELEMS / 4);
    split4(((const float4*)g_ao)[i],
           (__nv_bfloat162*)g_xh + i * 2, (__nv_bfloat162*)g_xl + i * 2);
    if (i < n4w)
        split4(wo[i], (__nv_bfloat162*)g_wh + i * 2, (__nv_bfloat162*)g_wl + i * 2);
}

// ---------------- HMMA bf16-split GEMM core ------------------------------------
#define GT_TILE  (128 * 80)
#define GT_STAGE (4 * GT_TILE)
#define GSMEM    (2 * GT_STAGE)

#define GEMM_ISSUE(ks, st) do {                                                 \
    const uint32_t ss = sb + (st) * GT_STAGE;                                   \
    size_t ga0 = ((size_t)(bm + r0) * DM + (ks) * 32 + kg0 * 8) * 2;            \
    size_t gb0 = ((size_t)(bn + r0) * DM + (ks) * 32 + kg0 * 8) * 2;            \
    size_t ga1 = ((size_t)(bm + r1) * DM + (ks) * 32 + kg1 * 8) * 2;            \
    size_t gb1 = ((size_t)(bn + r1) * DM + (ks) * 32 + kg1 * 8) * 2;            \
    uint32_t s0 = r0 * 80 + kg0 * 16, s1 = r1 * 80 + kg1 * 16;                  \
    cpa16(ss + 0 * GT_TILE + s0, pxh + ga0);                                    \
    cpa16(ss + 1 * GT_TILE + s0, pxl + ga0);                                    \
    cpa16(ss + 2 * GT_TILE + s0, pwh + gb0);                                    \
    cpa16(ss + 3 * GT_TILE + s0, pwl + gb0);                                    \
    cpa16(ss + 0 * GT_TILE + s1, pxh + ga1);                                    \
    cpa16(ss + 1 * GT_TILE + s1, pxl + ga1);                                    \
    cpa16(ss + 2 * GT_TILE + s1, pwh + gb1);                                    \
    cpa16(ss + 3 * GT_TILE + s1, pwl + gb1);                                    \
    asm volatile("cp.async.commit_group;" ::: "memory");                        \
} while (0)

#define GEMM_BODY()                                                             \
    GEMM_ISSUE(0, 0);                                                           \
    const int lrow = lane & 7;                                                  \
    const int sel  = lane >> 3;                                                 \
    const uint32_t fr_off = ((sel & 1) * 8 + lrow) * 80 + (sel >> 1) * 16;      \
    for (int ks = 0; ks < 32; ks++) {                                           \
        const int st = ks & 1;                                                  \
        if (ks + 1 < 32) {                                                      \
            GEMM_ISSUE(ks + 1, st ^ 1);                                         \
            asm volatile("cp.async.wait_group 1;" ::: "memory");                \
        } else {                                                                \
            asm volatile("cp.async.wait_group 0;" ::: "memory");                \
        }                                                                       \
        __syncthreads();                                                        \
        const uint32_t sAh = sb + st * GT_STAGE;                                \
        const uint32_t sAl = sAh + GT_TILE;                                     \
        const uint32_t sBh = sAh + 2 * GT_TILE;                                 \
        const uint32_t sBl = sAh + 3 * GT_TILE;                                 \
        _Pragma("unroll")                                                       \
        for (int k16 = 0; k16 < 2; k16++) {                                     \
            const uint32_t ko = fr_off + k16 * 32;                              \
            uint32_t ah[2][4], al[2][4], bh[4][4], bl[4][4];                    \
            _Pragma("unroll")                                                   \
            for (int mt = 0; mt < 2; mt++) {                                    \
                uint32_t base = (uint32_t)(wm * 32 + mt * 16) * 80 + ko;        \
                ldsm4(ah[mt], sAh + base);                                      \
                ldsm4(al[mt], sAl + base);                                      \
            }                                                                   \
            _Pragma("unroll")                                                   \
            for (int nq = 0; nq < 4; nq++) {                                    \
                uint32_t base = (uint32_t)(wn * 64 + nq * 16) * 80 + ko;        \
                ldsm4(bh[nq], sBh + base);                                      \
                ldsm4(bl[nq], sBl + base);                                      \
            }                                                                   \
            _Pragma("unroll")                                                   \
            for (int mt = 0; mt < 2; mt++)                                      \
                _Pragma("unroll")                                               \
                for (int nt = 0; nt < 8; nt++) {                                \
                    const int nq = nt >> 1, o = nt & 1;                         \
                    mma_bf16(acc[mt][nt], ah[mt], bh[nq][o], bh[nq][o + 2]);    \
                    mma_bf16(acc[mt][nt], ah[mt], bl[nq][o], bl[nq][o + 2]);    \
                    mma_bf16(acc[mt][nt], al[mt], bh[nq][o], bh[nq][o + 2]);    \
                }                                                               \
        }                                                                       \
        __syncthreads();                                                        \
    }

// fused Q/K/V projection: grid.z selects input/weight/bias/output set
__global__ void __launch_bounds__(256)
gemm_qkv(const float* __restrict__ bq, const float* __restrict__ bk,
         const float* __restrict__ bv)
{
    extern __shared__ char smem[];
    const uint32_t sb = smem_u32(smem);

    const int tid  = threadIdx.x;
    const int lane = tid & 31;
    const int wid  = tid >> 5;
    const int wm   = wid & 3;
    const int wn   = wid >> 2;
    const int bm   = blockIdx.y << 7;
    const int bn   = blockIdx.x << 7;
    const int z    = blockIdx.z;

    const char* pxh = (const char*)(g_xh + (size_t)z * XELEMS);
    const char* pxl = (const char*)(g_xl + (size_t)z * XELEMS);
    const char* pwh = (const char*)(g_wh + (size_t)z * WELEMS);
    const char* pwl = (const char*)(g_wl + (size_t)z * WELEMS);
    const float* bias = (z == 0) ? bq : (z == 1) ? bk : bv;
    __nv_bfloat16* ph = (z == 0) ? g_qh : (z == 1) ? g_kh : g_vh;
    __nv_bfloat16* pl = (z == 0) ? g_ql : (z == 1) ? g_kl : g_vl;
    const float qs = (z == 0) ? 0.18033688011112042f : 1.0f;   // 0.125*log2(e)

    float acc[2][8][4];
#pragma unroll
    for (int mt = 0; mt < 2; mt++)
#pragma unroll
        for (int nt = 0; nt < 8; nt++)
#pragma unroll
            for (int e = 0; e < 4; e++) acc[mt][nt][e] = 0.0f;

    const int r0 = tid >> 2, kg0 = tid & 3;
    const int r1 = (tid + 256) >> 2, kg1 = (tid + 256) & 3;

    GEMM_BODY()

    const int gid = lane >> 2;
    const int t4  = lane & 3;
#pragma unroll
    for (int mt = 0; mt < 2; mt++) {
#pragma unroll
        for (int nt = 0; nt < 8; nt++) {
            const int n0 = bn + wn * 64 + nt * 8 + t4 * 2;
            const float b0 = bias[n0], b1 = bias[n0 + 1];
#pragma unroll
            for (int half = 0; half < 2; half++) {
                const int m = bm + wm * 32 + mt * 16 + gid + half * 8;
                float vx = (acc[mt][nt][half * 2 + 0] + b0) * qs;
                float vy = (acc[mt][nt][half * 2 + 1] + b1) * qs;
                const int bb = m >> 11;
                const int s  = m & (S_LEN - 1);
                const int h  = n0 >> 6;
                const int d  = n0 & 63;
                __nv_bfloat16 hx = __float2bfloat16(vx);
                __nv_bfloat16 hy = __float2bfloat16(vy);
                __nv_bfloat16 lx = __float2bfloat16(vx - __bfloat162float(hx));
                __nv_bfloat16 ly = __float2bfloat16(vy - __bfloat162float(hy));
                size_t off = (((size_t)(bb * NH + h) * S_LEN) + s) * DKH + d;
                *(__nv_bfloat162*)(ph + off) = __nv_bfloat162(hx, hy);
                *(__nv_bfloat162*)(pl + off) = __nv_bfloat162(lx, ly);
            }
        }
    }
}

// output projection: reads slot-0 split buffers, writes fp32 [M, DM]
__global__ void __launch_bounds__(256)
gemm_out(const float* __restrict__ bias, float* __restrict__ Yout)
{
    extern __shared__ char smem[];
    const uint32_t sb = smem_u32(smem);

    const int tid  = threadIdx.x;
    const int lane = tid & 31;
    const int wid  = tid >> 5;
    const int wm   = wid & 3;
    const int wn   = wid >> 2;
    const int bm   = blockIdx.y << 7;
    const int bn   = blockIdx.x << 7;

    const char* pxh = (const char*)g_xh;
    const char* pxl = (const char*)g_xl;
    const char* pwh = (const char*)g_wh;
    const char* pwl = (const char*)g_wl;

    float acc[2][8][4];
#pragma unroll
    for (int mt = 0; mt < 2; mt++)
#pragma unroll
        for (int nt = 0; nt < 8; nt++)
#pragma unroll
            for (int e = 0; e < 4; e++) acc[mt][nt][e] = 0.0f;

    const int r0 = tid >> 2, kg0 = tid & 3;
    const int r1 = (tid + 256) >> 2, kg1 = (tid + 256) & 3;

    GEMM_BODY()

    const int gid = lane >> 2;
    const int t4  = lane & 3;
#pragma unroll
    for (int mt = 0; mt < 2; mt++) {
#pragma unroll
        for (int nt = 0; nt < 8; nt++) {
            const int n0 = bn + wn * 64 + nt * 8 + t4 * 2;
            const float b0 = bias[n0], b1 = bias[n0 + 1];
#pragma unroll
            for (int half = 0; half < 2; half++) {
                const int m = bm + wm * 32 + mt * 16 + gid + half * 8;
                float2 val;
                val.x = acc[mt][nt][half * 2 + 0] + b0;
                val.y = acc[mt][nt][half * 2 + 1] + b1;
                *(float2*)(Yout + (size_t)m * DM + n0) = val;
            }
        }
    }
}

// ---------------- HMMA flash attention (cp.async pipelined) --------------------
#define AT_S   144
#define AT_PS  272
#define AT_TSZ (128 * AT_S)
#define AT_PSZ (128 * AT_PS)
#define oQh 0
#define oQl (1 * AT_TSZ)
#define oKh (2 * AT_TSZ)
#define oKl (3 * AT_TSZ)
#define oVh (4 * AT_TSZ)
#define oVl (5 * AT_TSZ)
#define oPh (6 * AT_TSZ)
#define oPl (6 * AT_TSZ + AT_PSZ)
#define ASMEM (6 * AT_TSZ + 2 * AT_PSZ)   // 180224

__global__ void __launch_bounds__(256, 1)
attn_mma()
{
    extern __shared__ char sm[];
    const uint32_t sb = smem_u32(sm);

    const int tid  = threadIdx.x;
    const int lane = tid & 31;
    const int w    = tid >> 5;
    const int gid  = lane >> 2;
    const int t4   = lane & 3;
    const int lrow = lane & 7;
    const int sel  = lane >> 3;
    const int bh   = blockIdx.y;
    const int q0   = blockIdx.x << 7;

    const size_t hb = (size_t)bh * S_LEN * DKH;
    const __nv_bfloat16* gqh = g_qh + hb;
    const __nv_bfloat16* gql = g_ql + hb;
    const __nv_bfloat16* gkh = g_kh + hb;
    const __nv_bfloat16* gkl = g_kl + hb;
    const __nv_bfloat16* gvh = g_vh + hb;
    const __nv_bfloat16* gvl = g_vl + hb;

    // per-thread copy coords for a 128x64 bf16 tile (4 x 16B chunks)
    // idx = tid + p*256 -> r = idx>>3, g = idx&7
#define AKV_ISSUE(offH, offL, srcH, srcL, row0) do {                            \
    _Pragma("unroll")                                                           \
    for (int p = 0; p < 4; p++) {                                               \
        int idx = tid + (p << 8);                                               \
        int r = idx >> 3, g = idx & 7;                                          \
        uint32_t so = (uint32_t)r * AT_S + g * 16;                              \
        size_t ge = (size_t)((row0) + r) * DKH + g * 8;                         \
        cpa16(sb + (offH) + so, (srcH) + ge);                                   \
        cpa16(sb + (offL) + so, (srcL) + ge);                                   \
    }                                                                           \
    asm volatile("cp.async.commit_group;" ::: "memory");                        \
} while (0)

    // prologue: K(0) then V(0) in flight; load Q directly
    AKV_ISSUE(oKh, oKl, gkh, gkl, 0);
    AKV_ISSUE(oVh, oVl, gvh, gvl, 0);
#pragma unroll
    for (int p = 0; p < 4; p++) {
        int idx = tid + (p << 8);
        int r = idx >> 3, g = idx & 7;
        uint32_t so = (uint32_t)r * AT_S + g * 16;
        size_t ge = (size_t)(q0 + r) * DKH + g * 8;
        *(uint4*)(sm + oQh + so) = *(const uint4*)(gqh + ge);
        *(uint4*)(sm + oQl + so) = *(const uint4*)(gql + ge);
    }
    __syncthreads();

    const uint32_t frq = (uint32_t)((sel & 1) * 8 + lrow) * AT_S + (sel >> 1) * 16;
    uint32_t qfh[4][4], qfl[4][4];
#pragma unroll
    for (int k16 = 0; k16 < 4; k16++) {
        uint32_t a = sb + (uint32_t)(w * 16) * AT_S + frq + k16 * 32;
        ldsm4(qfh[k16], a + oQh);
        ldsm4(qfl[k16], a + oQl);
    }

    float m0 = -1e30f, m1 = -1e30f, l0 = 0.0f, l1 = 0.0f;
    float oacc[8][4];
#pragma unroll
    for (int nt = 0; nt < 8; nt++)
#pragma unroll
        for (int e = 0; e < 4; e++) oacc[nt][e] = 0.0f;

    for (int kt = 0; kt < S_LEN; kt += 128) {
        // K(kt) ready (allow 1 pending group = V(kt))
        asm volatile("cp.async.wait_group 1;" ::: "memory");
        __syncthreads();

        // ---- S = Q K^T ----
        float sacc[16][4];
#pragma unroll
        for (int nt = 0; nt < 16; nt++)
#pragma unroll
            for (int e = 0; e < 4; e++) sacc[nt][e] = 0.0f;

#pragma unroll
        for (int k16 = 0; k16 < 4; k16++) {
#pragma unroll
            for (int nb = 0; nb < 8; nb++) {
                uint32_t kbh[4], kbl[4];
                uint32_t off = sb + (uint32_t)(nb * 16) * AT_S + frq + k16 * 32;
                ldsm4(kbh, off + oKh);
                ldsm4(kbl, off + oKl);
                mma_bf16(sacc[nb * 2 + 0], qfh[k16], kbh[0], kbh[2]);
                mma_bf16(sacc[nb * 2 + 0], qfh[k16], kbl[0], kbl[2]);
                mma_bf16(sacc[nb * 2 + 0], qfl[k16], kbh[0], kbh[2]);
                mma_bf16(sacc[nb * 2 + 1], qfh[k16], kbh[1], kbh[3]);
                mma_bf16(sacc[nb * 2 + 1], qfh[k16], kbl[1], kbl[3]);
                mma_bf16(sacc[nb * 2 + 1], qfl[k16], kbh[1], kbh[3]);
            }
        }
        __syncthreads();   // all warps done reading K

        // prefetch K(next); wrap harmlessly on the last iteration
        {
            int nrow = (kt + 128) & (S_LEN - 1);
            AKV_ISSUE(oKh, oKl, gkh, gkl, nrow);
        }

        // ---- online softmax (exp2 domain) ----
        float mx0 = -1e30f, mx1 = -1e30f;
#pragma unroll
        for (int nt = 0; nt < 16; nt++) {
            mx0 = fmaxf(mx0, fmaxf(sacc[nt][0], sacc[nt][1]));
            mx1 = fmaxf(mx1, fmaxf(sacc[nt][2], sacc[nt][3]));
        }
        mx0 = fmaxf(mx0, __shfl_xor_sync(0xffffffffu, mx0, 1));
        mx0 = fmaxf(mx0, __shfl_xor_sync(0xffffffffu, mx0, 2));
        mx1 = fmaxf(mx1, __shfl_xor_sync(0xffffffffu, mx1, 1));
        mx1 = fmaxf(mx1, __shfl_xor_sync(0xffffffffu, mx1, 2));
        const float nm0 = fmaxf(m0, mx0);
        const float nm1 = fmaxf(m1, mx1);

        float rs0 = 0.0f, rs1 = 0.0f;
#pragma unroll
        for (int nt = 0; nt < 16; nt++) {
            sacc[nt][0] = ex2(sacc[nt][0] - nm0);
            sacc[nt][1] = ex2(sacc[nt][1] - nm0);
            sacc[nt][2] = ex2(sacc[nt][2] - nm1);
            sacc[nt][3] = ex2(sacc[nt][3] - nm1);
            rs0 += sacc[nt][0] + sacc[nt][1];
            rs1 += sacc[nt][2] + sacc[nt][3];
        }
        rs0 += __shfl_xor_sync(0xffffffffu, rs0, 1);
        rs0 += __shfl_xor_sync(0xffffffffu, rs0, 2);
        rs1 += __shfl_xor_sync(0xffffffffu, rs1, 1);
        rs1 += __shfl_xor_sync(0xffffffffu, rs1, 2);

        const float c0 = ex2(m0 - nm0);
        const float c1 = ex2(m1 - nm1);
        l0 = l0 * c0 + rs0;  m0 = nm0;
        l1 = l1 * c1 + rs1;  m1 = nm1;
#pragma unroll
        for (int nt = 0; nt < 8; nt++) {
            oacc[nt][0] *= c0; oacc[nt][1] *= c0;
            oacc[nt][2] *= c1; oacc[nt][3] *= c1;
        }

        // ---- store P (hi/lo) to warp-private smem rows ----
        const uint32_t pr0 = (uint32_t)(w * 16 + gid) * AT_PS + t4 * 4;
        const uint32_t pr1 = pr0 + 8 * AT_PS;
#pragma unroll
        for (int nt = 0; nt < 16; nt++) {
            const uint32_t co = nt * 16;
            float p0 = sacc[nt][0], p1 = sacc[nt][1];
            float p2 = sacc[nt][2], p3 = sacc[nt][3];
            __nv_bfloat16 h0 = __float2bfloat16(p0), h1 = __float2bfloat16(p1);
            __nv_bfloat16 h2 = __float2bfloat16(p2), h3 = __float2bfloat16(p3);
            __nv_bfloat16 e0 = __float2bfloat16(p0 - __bfloat162float(h0));
            __nv_bfloat16 e1 = __float2bfloat16(p1 - __bfloat162float(h1));
            __nv_bfloat16 e2 = __float2bfloat16(p2 - __bfloat162float(h2));
            __nv_bfloat16 e3 = __float2bfloat16(p3 - __bfloat162float(h3));
            *(__nv_bfloat162*)(sm + oPh + pr0 + co) = __nv_bfloat162(h0, h1);
            *(__nv_bfloat162*)(sm + oPl + pr0 + co) = __nv_bfloat162(e0, e1);
            *(__nv_bfloat162*)(sm + oPh + pr1 + co) = __nv_bfloat162(h2, h3);
            *(__nv_bfloat162*)(sm + oPl + pr1 + co) = __nv_bfloat162(e2, e3);
        }
        __syncwarp();

        // V(kt) ready (allow 1 pending group = K(kt+1))
        asm volatile("cp.async.wait_group 1;" ::: "memory");
        __syncthreads();

        // ---- O += P V ----
        const uint32_t frp = (uint32_t)(w * 16 + (sel & 1) * 8 + lrow) * AT_PS + (sel >> 1) * 16;
#pragma unroll
        for (int k16 = 0; k16 < 8; k16++) {
            uint32_t afh[4], afl[4];
            uint32_t pa = sb + frp + k16 * 32;
            ldsm4(afh, pa + oPh);
            ldsm4(afl, pa + oPl);
            const uint32_t vrow = sb + (uint32_t)(k16 * 16 + (lane & 15)) * AT_S;
#pragma unroll
            for (int dg = 0; dg < 4; dg++) {
                uint32_t vbh[4], vbl[4];
                uint32_t va = vrow + (uint32_t)(dg * 2 + (lane >> 4)) * 16;
                ldsm4t(vbh, va + oVh);
                ldsm4t(vbl, va + oVl);
                mma_bf16(oacc[dg * 2 + 0], afh, vbh[0], vbh[1]);
                mma_bf16(oacc[dg * 2 + 0], afh, vbl[0], vbl[1]);
                mma_bf16(oacc[dg * 2 + 0], afl, vbh[0], vbh[1]);
                mma_bf16(oacc[dg * 2 + 1], afh, vbh[2], vbh[3]);
                mma_bf16(oacc[dg * 2 + 1], afh, vbl[2], vbl[3]);
                mma_bf16(oacc[dg * 2 + 1], afl, vbh[2], vbh[3]);
            }
        }
        __syncthreads();   // all warps done reading V

        // prefetch V(next) unless last iteration
        if (kt + 128 < S_LEN)
            AKV_ISSUE(oVh, oVl, gvh, gvl, kt + 128);
    }

    asm volatile("cp.async.wait_group 0;" ::: "memory");   // drain wrap K load

    // ---- epilogue ----
    const int b = bh >> 4;
    const int h = bh & 15;
    const float inv0 = 1.0f / l0;
    const float inv1 = 1.0f / l1;
    const int r0 = q0 + w * 16 + gid;
    const int r1 = r0 + 8;
#pragma unroll
    for (int nt = 0; nt < 8; nt++) {
        const int col = (h << 6) + nt * 8 + t4 * 2;
        float2 v0, v1;
        v0.x = oacc[nt][0] * inv0; v0.y = oacc[nt][1] * inv0;
        v1.x = oacc[nt][2] * inv1; v1.y = oacc[nt][3] * inv1;
        *(float2*)(g_ao + (size_t)(b * S_LEN + r0) * DM + col) = v0;
        *(float2*)(g_ao + (size_t)(b * S_LEN + r1) * DM + col) = v1;
    }
#undef AKV_ISSUE
}

// ---------------------------------------------------------------------------
extern "C" void kernel_launch(void* const* d_in, const int* in_sizes, int n_in,
                              void* d_out, int out_size)
{
    const float* q  = (const float*)d_in[0];
    const float* k  = (const float*)d_in[1];
    const float* v  = (const float*)d_in[2];
    const float* wq = (const float*)d_in[3];
    const float* bq = (const float*)d_in[4];
    const float* wk = (const float*)d_in[5];
    const float* bk = (const float*)d_in[6];
    const float* wv = (const float*)d_in[7];
    const float* bv = (const float*)d_in[8];
    const float* wo = (const float*)d_in[9];
    const float* bo = (const float*)d_in[10];
    float* out = (float*)d_out;

    cudaFuncSetAttribute(gemm_qkv, cudaFuncAttributeMaxDynamicSharedMemorySize, GSMEM);
    cudaFuncSetAttribute(gemm_out, cudaFuncAttributeMaxDynamicSharedMemorySize, GSMEM);
    cudaFuncSetAttribute(attn_mma, cudaFuncAttributeMaxDynamicSharedMemorySize, ASMEM);

    const int bx = (int)(XELEMS / 4 / 256);   // 4096
    const int bw = (int)(WELEMS / 4 / 256);   // 1024

    conv_x3<<<dim3(bx, 3), 256>>>((const float4*)q, (const float4*)k, (const float4*)v);
    conv_w3<<<dim3(bw, 3), 256>>>((const float4*)wq, (const float4*)wk, (const float4*)wv);
    gemm_qkv<<<dim3(8, 32, 3), 256, GSMEM>>>(bq, bk, bv);
    attn_mma<<<dim3(S_LEN / 128, B_SZ * NH), 256, ASMEM>>>();
    conv_ao_wo<<<bx, 256>>>((const float4*)wo);
    gemm_out<<<dim3(8, 32), 256, GSMEM>>>(bo, out);
}

// round 8
// speedup vs baseline: 2.7900x; 1.1116x over previous
#include <cuda_runtime.h>
#include <cuda_bf16.h>
#include <cstdint>

#define B_SZ   2
#define S_LEN  2048
#define DM     1024
#define NH     16
#define DKH    64
#define M_ROWS (B_SZ * S_LEN)   // 4096
#define XELEMS ((size_t)M_ROWS * DM)
#define WELEMS ((size_t)DM * DM)

// ---------------- scratch ----------------------------------------------------
__device__ __align__(16) float g_ao[XELEMS];
__device__ __align__(16) __nv_bfloat16 g_xh[3 * XELEMS];
__device__ __align__(16) __nv_bfloat16 g_xl[3 * XELEMS];
__device__ __align__(16) __nv_bfloat16 g_wh[3 * WELEMS];
__device__ __align__(16) __nv_bfloat16 g_wl[3 * WELEMS];
__device__ __align__(16) __nv_bfloat16 g_qh[(size_t)B_SZ * NH * S_LEN * DKH];
__device__ __align__(16) __nv_bfloat16 g_ql[(size_t)B_SZ * NH * S_LEN * DKH];
__device__ __align__(16) __nv_bfloat16 g_kh[(size_t)B_SZ * NH * S_LEN * DKH];
__device__ __align__(16) __nv_bfloat16 g_kl[(size_t)B_SZ * NH * S_LEN * DKH];
__device__ __align__(16) __nv_bfloat16 g_vh[(size_t)B_SZ * NH * S_LEN * DKH];
__device__ __align__(16) __nv_bfloat16 g_vl[(size_t)B_SZ * NH * S_LEN * DKH];

// ---------------- helpers -----------------------------------------------------
__device__ __forceinline__ uint32_t smem_u32(const void* p) {
    uint32_t a;
    asm("{ .reg .u64 t; cvta.to.shared.u64 t, %1; cvt.u32.u64 %0, t; }"
        : "=r"(a) : "l"(p));
    return a;
}
__device__ __forceinline__ void cpa16(uint32_t s, const void* g) {
    asm volatile("cp.async.cg.shared.global [%0], [%1], 16;" :: "r"(s), "l"(g) : "memory");
}
__device__ __forceinline__ void ldsm4(uint32_t r[4], uint32_t addr) {
    asm volatile("ldmatrix.sync.aligned.m8n8.x4.shared.b16 {%0,%1,%2,%3}, [%4];"
                 : "=r"(r[0]), "=r"(r[1]), "=r"(r[2]), "=r"(r[3]) : "r"(addr));
}
__device__ __forceinline__ void ldsm4t(uint32_t r[4], uint32_t addr) {
    asm volatile("ldmatrix.sync.aligned.m8n8.x4.trans.shared.b16 {%0,%1,%2,%3}, [%4];"
                 : "=r"(r[0]), "=r"(r[1]), "=r"(r[2]), "=r"(r[3]) : "r"(addr));
}
__device__ __forceinline__ void mma_bf16(float d[4], const uint32_t a[4],
                                         uint32_t b0, uint32_t b1) {
    asm volatile(
        "mma.sync.aligned.m16n8k16.row.col.f32.bf16.bf16.f32 "
        "{%0,%1,%2,%3},{%4,%5,%6,%7},{%8,%9},{%0,%1,%2,%3};"
        : "+f"(d[0]), "+f"(d[1]), "+f"(d[2]), "+f"(d[3])
        : "r"(a[0]), "r"(a[1]), "r"(a[2]), "r"(a[3]), "r"(b0), "r"(b1));
}
__device__ __forceinline__ float ex2(float x) {
    float y; asm("ex2.approx.ftz.f32 %0, %1;" : "=f"(y) : "f"(x)); return y;
}
__device__ __forceinline__ uint32_t pkbf2(float lo, float hi) {
    uint32_t r;
    asm("cvt.rn.bf16x2.f32 %0, %1, %2;" : "=r"(r) : "f"(hi), "f"(lo));
    return r;
}
__device__ __forceinline__ float bf_hi(float x) {
    return __bfloat162float(__float2bfloat16(x));
}
__device__ __forceinline__ void split4(float4 v, __nv_bfloat162* hi, __nv_bfloat162* lo) {
    __nv_bfloat16 h0 = __float2bfloat16(v.x);
    __nv_bfloat16 h1 = __float2bfloat16(v.y);
    __nv_bfloat16 h2 = __float2bfloat16(v.z);
    __nv_bfloat16 h3 = __float2bfloat16(v.w);
    __nv_bfloat16 l0 = __float2bfloat16(v.x - __bfloat162float(h0));
    __nv_bfloat16 l1 = __float2bfloat16(v.y - __bfloat162float(h1));
    __nv_bfloat16 l2 = __float2bfloat16(v.z - __bfloat162float(h2));
    __nv_bfloat16 l3 = __float2bfloat16(v.w - __bfloat162float(h3));
    hi[0] = __nv_bfloat162(h0, h1); hi[1] = __nv_bfloat162(h2, h3);
    lo[0] = __nv_bfloat162(l0, l1); lo[1] = __nv_bfloat162(l2, l3);
}

// ---------------- fp32 -> bf16 hi/lo split kernels -----------------------------
__global__ void __launch_bounds__(256)
conv_x3(const float4* __restrict__ q, const float4* __restrict__ k,
        const float4* __restrict__ v)
{
    const int y = blockIdx.y;
    const float4* src = (y == 0) ? q : (y == 1) ? k : v;
    __nv_bfloat162* hi = (__nv_bfloat162*)(g_xh + (size_t)y * XELEMS);
    __nv_bfloat162* lo = (__nv_bfloat162*)(g_xl + (size_t)y * XELEMS);
    int i = blockIdx.x * 256 + threadIdx.x;
    split4(src[i], hi + i * 2, lo + i * 2);
}
__global__ void __launch_bounds__(256)
conv_w3(const float4* __restrict__ wq, const float4* __restrict__ wk,
        const float4* __restrict__ wv)
{
    const int y = blockIdx.y;
    const float4* src = (y == 0) ? wq : (y == 1) ? wk : wv;
    __nv_bfloat162* hi = (__nv_bfloat162*)(g_wh + (size_t)y * WELEMS);
    __nv_bfloat162* lo = (__nv_bfloat162*)(g_wl + (size_t)y * WELEMS);
    int i = blockIdx.x * 256 + threadIdx.x;
    split4(src[i], hi + i * 2, lo + i * 2);
}
__global__ void __launch_bounds__(256)
conv_ao_wo(const float4* __restrict__ wo)
{
    int i = blockIdx.x * 256 + threadIdx.x;
    const int n4w = (int)(WELEMS / 4);
    split4(((const float4*)g_ao)[i],
           (__nv_bfloat162*)g_xh + i * 2, (__nv_bfloat162*)g_xl + i * 2);
    if (i < n4w)
        split4(wo[i], (__nv_bfloat162*)g_wh + i * 2, (__nv_bfloat162*)g_wl + i * 2);
}

// ---------------- HMMA bf16-split GEMM core ------------------------------------
#define GT_TILE  (128 * 80)
#define GT_STAGE (4 * GT_TILE)
#define GSMEM    (2 * GT_STAGE)

#define GEMM_ISSUE(ks, st) do {                                                 \
    const uint32_t ss = sb + (st) * GT_STAGE;                                   \
    size_t ga0 = ((size_t)(bm + r0) * DM + (ks) * 32 + kg0 * 8) * 2;            \
    size_t gb0 = ((size_t)(bn + r0) * DM + (ks) * 32 + kg0 * 8) * 2;            \
    size_t ga1 = ((size_t)(bm + r1) * DM + (ks) * 32 + kg1 * 8) * 2;            \
    size_t gb1 = ((size_t)(bn + r1) * DM + (ks) * 32 + kg1 * 8) * 2;            \
    uint32_t s0 = r0 * 80 + kg0 * 16, s1 = r1 * 80 + kg1 * 16;                  \
    cpa16(ss + 0 * GT_TILE + s0, pxh + ga0);                                    \
    cpa16(ss + 1 * GT_TILE + s0, pxl + ga0);                                    \
    cpa16(ss + 2 * GT_TILE + s0, pwh + gb0);                                    \
    cpa16(ss + 3 * GT_TILE + s0, pwl + gb0);                                    \
    cpa16(ss + 0 * GT_TILE + s1, pxh + ga1);                                    \
    cpa16(ss + 1 * GT_TILE + s1, pxl + ga1);                                    \
    cpa16(ss + 2 * GT_TILE + s1, pwh + gb1);                                    \
    cpa16(ss + 3 * GT_TILE + s1, pwl + gb1);                                    \
    asm volatile("cp.async.commit_group;" ::: "memory");                        \
} while (0)

#define GEMM_BODY()                                                             \
    GEMM_ISSUE(0, 0);                                                           \
    const int lrow = lane & 7;                                                  \
    const int sel  = lane >> 3;                                                 \
    const uint32_t fr_off = ((sel & 1) * 8 + lrow) * 80 + (sel >> 1) * 16;      \
    for (int ks = 0; ks < 32; ks++) {                                           \
        const int st = ks & 1;                                                  \
        if (ks + 1 < 32) {                                                      \
            GEMM_ISSUE(ks + 1, st ^ 1);                                         \
            asm volatile("cp.async.wait_group 1;" ::: "memory");                \
        } else {                                                                \
            asm volatile("cp.async.wait_group 0;" ::: "memory");                \
        }                                                                       \
        __syncthreads();                                                        \
        const uint32_t sAh = sb + st * GT_STAGE;                                \
        const uint32_t sAl = sAh + GT_TILE;                                     \
        const uint32_t sBh = sAh + 2 * GT_TILE;                                 \
        const uint32_t sBl = sAh + 3 * GT_TILE;                                 \
        _Pragma("unroll")                                                       \
        for (int k16 = 0; k16 < 2; k16++) {                                     \
            const uint32_t ko = fr_off + k16 * 32;                              \
            uint32_t ah[2][4], al[2][4], bh[4][4], bl[4][4];                    \
            _Pragma("unroll")                                                   \
            for (int mt = 0; mt < 2; mt++) {                                    \
                uint32_t base = (uint32_t)(wm * 32 + mt * 16) * 80 + ko;        \
                ldsm4(ah[mt], sAh + base);                                      \
                ldsm4(al[mt], sAl + base);                                      \
            }                                                                   \
            _Pragma("unroll")                                                   \
            for (int nq = 0; nq < 4; nq++) {                                    \
                uint32_t base = (uint32_t)(wn * 64 + nq * 16) * 80 + ko;        \
                ldsm4(bh[nq], sBh + base);                                      \
                ldsm4(bl[nq], sBl + base);                                      \
            }                                                                   \
            _Pragma("unroll")                                                   \
            for (int mt = 0; mt < 2; mt++)                                      \
                _Pragma("unroll")                                               \
                for (int nt = 0; nt < 8; nt++) {                                \
                    const int nq = nt >> 1, o = nt & 1;                         \
                    mma_bf16(acc[mt][nt], ah[mt], bh[nq][o], bh[nq][o + 2]);    \
                    mma_bf16(acc[mt][nt], ah[mt], bl[nq][o], bl[nq][o + 2]);    \
                    mma_bf16(acc[mt][nt], al[mt], bh[nq][o], bh[nq][o + 2]);    \
                }                                                               \
        }                                                                       \
        __syncthreads();                                                        \
    }

__global__ void __launch_bounds__(256)
gemm_qkv(const float* __restrict__ bq, const float* __restrict__ bk,
         const float* __restrict__ bv)
{
    extern __shared__ char smem[];
    const uint32_t sb = smem_u32(smem);

    const int tid  = threadIdx.x;
    const int lane = tid & 31;
    const int wid  = tid >> 5;
    const int wm   = wid & 3;
    const int wn   = wid >> 2;
    const int bm   = blockIdx.y << 7;
    const int bn   = blockIdx.x << 7;
    const int z    = blockIdx.z;

    const char* pxh = (const char*)(g_xh + (size_t)z * XELEMS);
    const char* pxl = (const char*)(g_xl + (size_t)z * XELEMS);
    const char* pwh = (const char*)(g_wh + (size_t)z * WELEMS);
    const char* pwl = (const char*)(g_wl + (size_t)z * WELEMS);
    const float* bias = (z == 0) ? bq : (z == 1) ? bk : bv;
    __nv_bfloat16* ph = (z == 0) ? g_qh : (z == 1) ? g_kh : g_vh;
    __nv_bfloat16* pl = (z == 0) ? g_ql : (z == 1) ? g_kl : g_vl;
    const float qs = (z == 0) ? 0.18033688011112042f : 1.0f;   // 0.125*log2(e)

    float acc[2][8][4];
#pragma unroll
    for (int mt = 0; mt < 2; mt++)
#pragma unroll
        for (int nt = 0; nt < 8; nt++)
#pragma unroll
            for (int e = 0; e < 4; e++) acc[mt][nt][e] = 0.0f;

    const int r0 = tid >> 2, kg0 = tid & 3;
    const int r1 = (tid + 256) >> 2, kg1 = (tid + 256) & 3;

    GEMM_BODY()

    const int gid = lane >> 2;
    const int t4  = lane & 3;
#pragma unroll
    for (int mt = 0; mt < 2; mt++) {
#pragma unroll
        for (int nt = 0; nt < 8; nt++) {
            const int n0 = bn + wn * 64 + nt * 8 + t4 * 2;
            const float b0 = bias[n0], b1 = bias[n0 + 1];
#pragma unroll
            for (int half = 0; half < 2; half++) {
                const int m = bm + wm * 32 + mt * 16 + gid + half * 8;
                float vx = (acc[mt][nt][half * 2 + 0] + b0) * qs;
                float vy = (acc[mt][nt][half * 2 + 1] + b1) * qs;
                const int bb = m >> 11;
                const int s  = m & (S_LEN - 1);
                const int h  = n0 >> 6;
                const int d  = n0 & 63;
                __nv_bfloat16 hx = __float2bfloat16(vx);
                __nv_bfloat16 hy = __float2bfloat16(vy);
                __nv_bfloat16 lx = __float2bfloat16(vx - __bfloat162float(hx));
                __nv_bfloat16 ly = __float2bfloat16(vy - __bfloat162float(hy));
                size_t off = (((size_t)(bb * NH + h) * S_LEN) + s) * DKH + d;
                *(__nv_bfloat162*)(ph + off) = __nv_bfloat162(hx, hy);
                *(__nv_bfloat162*)(pl + off) = __nv_bfloat162(lx, ly);
            }
        }
    }
}

__global__ void __launch_bounds__(256)
gemm_out(const float* __restrict__ bias, float* __restrict__ Yout)
{
    extern __shared__ char smem[];
    const uint32_t sb = smem_u32(smem);

    const int tid  = threadIdx.x;
    const int lane = tid & 31;
    const int wid  = tid >> 5;
    const int wm   = wid & 3;
    const int wn   = wid >> 2;
    const int bm   = blockIdx.y << 7;
    const int bn   = blockIdx.x << 7;

    const char* pxh = (const char*)g_xh;
    const char* pxl = (const char*)g_xl;
    const char* pwh = (const char*)g_wh;
    const char* pwl = (const char*)g_wl;

    float acc[2][8][4];
#pragma unroll
    for (int mt = 0; mt < 2; mt++)
#pragma unroll
        for (int nt = 0; nt < 8; nt++)
#pragma unroll
            for (int e = 0; e < 4; e++) acc[mt][nt][e] = 0.0f;

    const int r0 = tid >> 2, kg0 = tid & 3;
    const int r1 = (tid + 256) >> 2, kg1 = (tid + 256) & 3;

    GEMM_BODY()

    const int gid = lane >> 2;
    const int t4  = lane & 3;
#pragma unroll
    for (int mt = 0; mt < 2; mt++) {
#pragma unroll
        for (int nt = 0; nt < 8; nt++) {
            const int n0 = bn + wn * 64 + nt * 8 + t4 * 2;
            const float b0 = bias[n0], b1 = bias[n0 + 1];
#pragma unroll
            for (int half = 0; half < 2; half++) {
                const int m = bm + wm * 32 + mt * 16 + gid + half * 8;
                float2 val;
                val.x = acc[mt][nt][half * 2 + 0] + b0;
                val.y = acc[mt][nt][half * 2 + 1] + b1;
                *(float2*)(Yout + (size_t)m * DM + n0) = val;
            }
        }
    }
}

// ---------------- HMMA flash attention v3 --------------------------------------
// CTA = (bh, 64 q rows), 4 warps x 16 rows, 128 threads, 2 CTAs/SM.
// P kept in registers (C-fragment == A-fragment layout); no P smem round trip.
#define AT_S    144
#define AQ_TSZ  (64 * AT_S)      //  9216
#define AKV_TSZ (128 * AT_S)     // 18432
#define oQh 0
#define oQl (AQ_TSZ)
#define oKh (2 * AQ_TSZ)
#define oKl (2 * AQ_TSZ + AKV_TSZ)
#define oVh (2 * AQ_TSZ + 2 * AKV_TSZ)
#define oVl (2 * AQ_TSZ + 3 * AKV_TSZ)
#define ASMEM (2 * AQ_TSZ + 4 * AKV_TSZ)   // 92160

__global__ void __launch_bounds__(128, 2)
attn_mma()
{
    extern __shared__ char sm[];
    const uint32_t sb = smem_u32(sm);

    const int tid  = threadIdx.x;
    const int lane = tid & 31;
    const int w    = tid >> 5;          // 0..3
    const int gid  = lane >> 2;
    const int t4   = lane & 3;
    const int lrow = lane & 7;
    const int sel  = lane >> 3;
    const int bh   = blockIdx.y;
    const int q0   = blockIdx.x << 6;   // 64-row q tile

    const size_t hb = (size_t)bh * S_LEN * DKH;
    const __nv_bfloat16* gqh = g_qh + hb;
    const __nv_bfloat16* gql = g_ql + hb;
    const __nv_bfloat16* gkh = g_kh + hb;
    const __nv_bfloat16* gkl = g_kl + hb;
    const __nv_bfloat16* gvh = g_vh + hb;
    const __nv_bfloat16* gvl = g_vl + hb;

    // 128x64 bf16 tile copy: 1024 chunks of 16B, 128 threads -> 8 per thread
#define AKV_ISSUE(offH, offL, srcH, srcL, row0) do {                            \
    _Pragma("unroll")                                                           \
    for (int p = 0; p < 8; p++) {                                               \
        int idx = tid + (p << 7);                                               \
        int r = idx >> 3, g = idx & 7;                                          \
        uint32_t so = (uint32_t)r * AT_S + g * 16;                              \
        size_t ge = (size_t)((row0) + r) * DKH + g * 8;                         \
        cpa16(sb + (offH) + so, (srcH) + ge);                                   \
        cpa16(sb + (offL) + so, (srcL) + ge);                                   \
    }                                                                           \
    asm volatile("cp.async.commit_group;" ::: "memory");                        \
} while (0)

    AKV_ISSUE(oKh, oKl, gkh, gkl, 0);
    AKV_ISSUE(oVh, oVl, gvh, gvl, 0);
    // Q tile: 64 rows -> 512 chunks, 4 per thread per buffer
#pragma unroll
    for (int p = 0; p < 4; p++) {
        int idx = tid + (p << 7);
        int r = idx >> 3, g = idx & 7;
        uint32_t so = (uint32_t)r * AT_S + g * 16;
        size_t ge = (size_t)(q0 + r) * DKH + g * 8;
        *(uint4*)(sm + oQh + so) = *(const uint4*)(gqh + ge);
        *(uint4*)(sm + oQl + so) = *(const uint4*)(gql + ge);
    }
    __syncthreads();

    const uint32_t frq = (uint32_t)((sel & 1) * 8 + lrow) * AT_S + (sel >> 1) * 16;
    uint32_t qfh[4][4], qfl[4][4];
#pragma unroll
    for (int k16 = 0; k16 < 4; k16++) {
        uint32_t a = sb + (uint32_t)(w * 16) * AT_S + frq + k16 * 32;
        ldsm4(qfh[k16], a + oQh);
        ldsm4(qfl[k16], a + oQl);
    }

    float m0 = -1e30f, m1 = -1e30f, l0 = 0.0f, l1 = 0.0f;
    float oacc[8][4];
#pragma unroll
    for (int nt = 0; nt < 8; nt++)
#pragma unroll
        for (int e = 0; e < 4; e++) oacc[nt][e] = 0.0f;

    for (int kt = 0; kt < S_LEN; kt += 128) {
        asm volatile("cp.async.wait_group 1;" ::: "memory");   // K(kt) ready
        __syncthreads();

        // ---- S = Q K^T ----
        float sacc[16][4];
#pragma unroll
        for (int nt = 0; nt < 16; nt++)
#pragma unroll
            for (int e = 0; e < 4; e++) sacc[nt][e] = 0.0f;

#pragma unroll
        for (int k16 = 0; k16 < 4; k16++) {
#pragma unroll
            for (int nb = 0; nb < 8; nb++) {
                uint32_t kbh[4], kbl[4];
                uint32_t off = sb + (uint32_t)(nb * 16) * AT_S + frq + k16 * 32;
                ldsm4(kbh, off + oKh);
                ldsm4(kbl, off + oKl);
                mma_bf16(sacc[nb * 2 + 0], qfh[k16], kbh[0], kbh[2]);
                mma_bf16(sacc[nb * 2 + 0], qfh[k16], kbl[0], kbl[2]);
                mma_bf16(sacc[nb * 2 + 0], qfl[k16], kbh[0], kbh[2]);
                mma_bf16(sacc[nb * 2 + 1], qfh[k16], kbh[1], kbh[3]);
                mma_bf16(sacc[nb * 2 + 1], qfh[k16], kbl[1], kbl[3]);
                mma_bf16(sacc[nb * 2 + 1], qfl[k16], kbh[1], kbh[3]);
            }
        }
        __syncthreads();   // all warps done reading K

        if (kt + 128 < S_LEN)
            AKV_ISSUE(oKh, oKl, gkh, gkl, kt + 128);   // prefetch K(next)

        // ---- online softmax (exp2 domain, intra-warp) ----
        float mx0 = -1e30f, mx1 = -1e30f;
#pragma unroll
        for (int nt = 0; nt < 16; nt++) {
            mx0 = fmaxf(mx0, fmaxf(sacc[nt][0], sacc[nt][1]));
            mx1 = fmaxf(mx1, fmaxf(sacc[nt][2], sacc[nt][3]));
        }
        mx0 = fmaxf(mx0, __shfl_xor_sync(0xffffffffu, mx0, 1));
        mx0 = fmaxf(mx0, __shfl_xor_sync(0xffffffffu, mx0, 2));
        mx1 = fmaxf(mx1, __shfl_xor_sync(0xffffffffu, mx1, 1));
        mx1 = fmaxf(mx1, __shfl_xor_sync(0xffffffffu, mx1, 2));
        const float nm0 = fmaxf(m0, mx0);
        const float nm1 = fmaxf(m1, mx1);

        float rs0 = 0.0f, rs1 = 0.0f;
#pragma unroll
        for (int nt = 0; nt < 16; nt++) {
            sacc[nt][0] = ex2(sacc[nt][0] - nm0);
            sacc[nt][1] = ex2(sacc[nt][1] - nm0);
            sacc[nt][2] = ex2(sacc[nt][2] - nm1);
            sacc[nt][3] = ex2(sacc[nt][3] - nm1);
            rs0 += sacc[nt][0] + sacc[nt][1];
            rs1 += sacc[nt][2] + sacc[nt][3];
        }
        rs0 += __shfl_xor_sync(0xffffffffu, rs0, 1);
        rs0 += __shfl_xor_sync(0xffffffffu, rs0, 2);
        rs1 += __shfl_xor_sync(0xffffffffu, rs1, 1);
        rs1 += __shfl_xor_sync(0xffffffffu, rs1, 2);

        const float c0 = ex2(m0 - nm0);
        const float c1 = ex2(m1 - nm1);
        l0 = l0 * c0 + rs0;  m0 = nm0;
        l1 = l1 * c1 + rs1;  m1 = nm1;
#pragma unroll
        for (int nt = 0; nt < 8; nt++) {
            oacc[nt][0] *= c0; oacc[nt][1] *= c0;
            oacc[nt][2] *= c1; oacc[nt][3] *= c1;
        }

        asm volatile("cp.async.wait_group 1;" ::: "memory");   // V(kt) ready
        __syncthreads();

        // ---- O += P V, P packed from registers (C-frag == A-frag layout) ----
#pragma unroll
        for (int j = 0; j < 8; j++) {
            // hi fragments + lo residual fragments for kv cols 16j..16j+15
            float h00 = bf_hi(sacc[2*j][0]),   h01 = bf_hi(sacc[2*j][1]);
            float h02 = bf_hi(sacc[2*j][2]),   h03 = bf_hi(sacc[2*j][3]);
            float h10 = bf_hi(sacc[2*j+1][0]), h11 = bf_hi(sacc[2*j+1][1]);
            float h12 = bf_hi(sacc[2*j+1][2]), h13 = bf_hi(sacc[2*j+1][3]);
            uint32_t afh[4], afl[4];
            afh[0] = pkbf2(h00, h01);
            afh[1] = pkbf2(h02, h03);
            afh[2] = pkbf2(h10, h11);
            afh[3] = pkbf2(h12, h13);
            afl[0] = pkbf2(sacc[2*j][0]   - h00, sacc[2*j][1]   - h01);
            afl[1] = pkbf2(sacc[2*j][2]   - h02, sacc[2*j][3]   - h03);
            afl[2] = pkbf2(sacc[2*j+1][0] - h10, sacc[2*j+1][1] - h11);
            afl[3] = pkbf2(sacc[2*j+1][2] - h12, sacc[2*j+1][3] - h13);

            const uint32_t vrow = sb + (uint32_t)(j * 16 + (lane & 15)) * AT_S;
#pragma unroll
            for (int dg = 0; dg < 4; dg++) {
                uint32_t vbh[4], vbl[4];
                uint32_t va = vrow + (uint32_t)(dg * 2 + (lane >> 4)) * 16;
                ldsm4t(vbh, va + oVh);
                ldsm4t(vbl, va + oVl);
                mma_bf16(oacc[dg * 2 + 0], afh, vbh[0], vbh[1]);
                mma_bf16(oacc[dg * 2 + 0], afh, vbl[0], vbl[1]);
                mma_bf16(oacc[dg * 2 + 0], afl, vbh[0], vbh[1]);
                mma_bf16(oacc[dg * 2 + 1], afh, vbh[2], vbh[3]);
                mma_bf16(oacc[dg * 2 + 1], afh, vbl[2], vbl[3]);
                mma_bf16(oacc[dg * 2 + 1], afl, vbh[2], vbh[3]);
            }
        }
        __syncthreads();   // all warps done reading V

        if (kt + 128 < S_LEN)
            AKV_ISSUE(oVh, oVl, gvh, gvl, kt + 128);   // prefetch V(next)
    }

    // ---- epilogue ----
    const int b = bh >> 4;
    const int h = bh & 15;
    const float inv0 = 1.0f / l0;
    const float inv1 = 1.0f / l1;
    const int r0 = q0 + w * 16 + gid;
    const int r1 = r0 + 8;
#pragma unroll
    for (int nt = 0; nt < 8; nt++) {
        const int col = (h << 6) + nt * 8 + t4 * 2;
        float2 v0, v1;
        v0.x = oacc[nt][0] * inv0; v0.y = oacc[nt][1] * inv0;
        v1.x = oacc[nt][2] * inv1; v1.y = oacc[nt][3] * inv1;
        *(float2*)(g_ao + (size_t)(b * S_LEN + r0) * DM + col) = v0;
        *(float2*)(g_ao + (size_t)(b * S_LEN + r1) * DM + col) = v1;
    }
#undef AKV_ISSUE
}

// ---------------------------------------------------------------------------
extern "C" void kernel_launch(void* const* d_in, const int* in_sizes, int n_in,
                              void* d_out, int out_size)
{
    const float* q  = (const float*)d_in[0];
    const float* k  = (const float*)d_in[1];
    const float* v  = (const float*)d_in[2];
    const float* wq = (const float*)d_in[3];
    const float* bq = (const float*)d_in[4];
    const float* wk = (const float*)d_in[5];
    const float* bk = (const float*)d_in[6];
    const float* wv = (const float*)d_in[7];
    const float* bv = (const float*)d_in[8];
    const float* wo = (const float*)d_in[9];
    const float* bo = (const float*)d_in[10];
    float* out = (float*)d_out;

    cudaFuncSetAttribute(gemm_qkv, cudaFuncAttributeMaxDynamicSharedMemorySize, GSMEM);
    cudaFuncSetAttribute(gemm_out, cudaFuncAttributeMaxDynamicSharedMemorySize, GSMEM);
    cudaFuncSetAttribute(attn_mma, cudaFuncAttributeMaxDynamicSharedMemorySize, ASMEM);

    const int bx = (int)(XELEMS / 4 / 256);   // 4096
    const int bw = (int)(WELEMS / 4 / 256);   // 1024

    conv_x3<<<dim3(bx, 3), 256>>>((const float4*)q, (const float4*)k, (const float4*)v);
    conv_w3<<<dim3(bw, 3), 256>>>((const float4*)wq, (const float4*)wk, (const float4*)wv);
    gemm_qkv<<<dim3(8, 32, 3), 256, GSMEM>>>(bq, bk, bv);
    attn_mma<<<dim3(S_LEN / 64, B_SZ * NH), 128, ASMEM>>>();
    conv_ao_wo<<<bx, 256>>>((const float4*)wo);
    gemm_out<<<dim3(8, 32), 256, GSMEM>>>(bo, out);
}

// round 9
// speedup vs baseline: 2.8005x; 1.0038x over previous
#include <cuda_runtime.h>
#include <cuda_bf16.h>
#include <cstdint>

#define B_SZ   2
#define S_LEN  2048
#define DM     1024
#define NH     16
#define DKH    64
#define M_ROWS (B_SZ * S_LEN)   // 4096
#define XELEMS ((size_t)M_ROWS * DM)
#define WELEMS ((size_t)DM * DM)

// ---------------- scratch ----------------------------------------------------
__device__ __align__(16) __nv_bfloat16 g_xh[3 * XELEMS];
__device__ __align__(16) __nv_bfloat16 g_xl[3 * XELEMS];
__device__ __align__(16) __nv_bfloat16 g_wh[4 * WELEMS];
__device__ __align__(16) __nv_bfloat16 g_wl[4 * WELEMS];
__device__ __align__(16) __nv_bfloat16 g_qh[(size_t)B_SZ * NH * S_LEN * DKH];
__device__ __align__(16) __nv_bfloat16 g_ql[(size_t)B_SZ * NH * S_LEN * DKH];
__device__ __align__(16) __nv_bfloat16 g_kh[(size_t)B_SZ * NH * S_LEN * DKH];
__device__ __align__(16) __nv_bfloat16 g_kl[(size_t)B_SZ * NH * S_LEN * DKH];
__device__ __align__(16) __nv_bfloat16 g_vh[(size_t)B_SZ * NH * S_LEN * DKH];
__device__ __align__(16) __nv_bfloat16 g_vl[(size_t)B_SZ * NH * S_LEN * DKH];

// ---------------- helpers -----------------------------------------------------
__device__ __forceinline__ uint32_t smem_u32(const void* p) {
    uint32_t a;
    asm("{ .reg .u64 t; cvta.to.shared.u64 t, %1; cvt.u32.u64 %0, t; }"
        : "=r"(a) : "l"(p));
    return a;
}
__device__ __forceinline__ void cpa16(uint32_t s, const void* g) {
    asm volatile("cp.async.cg.shared.global [%0], [%1], 16;" :: "r"(s), "l"(g) : "memory");
}
__device__ __forceinline__ void ldsm4(uint32_t r[4], uint32_t addr) {
    asm volatile("ldmatrix.sync.aligned.m8n8.x4.shared.b16 {%0,%1,%2,%3}, [%4];"
                 : "=r"(r[0]), "=r"(r[1]), "=r"(r[2]), "=r"(r[3]) : "r"(addr));
}
__device__ __forceinline__ void ldsm4t(uint32_t r[4], uint32_t addr) {
    asm volatile("ldmatrix.sync.aligned.m8n8.x4.trans.shared.b16 {%0,%1,%2,%3}, [%4];"
                 : "=r"(r[0]), "=r"(r[1]), "=r"(r[2]), "=r"(r[3]) : "r"(addr));
}
__device__ __forceinline__ void mma_bf16(float d[4], const uint32_t a[4],
                                         uint32_t b0, uint32_t b1) {
    asm volatile(
        "mma.sync.aligned.m16n8k16.row.col.f32.bf16.bf16.f32 "
        "{%0,%1,%2,%3},{%4,%5,%6,%7},{%8,%9},{%0,%1,%2,%3};"
        : "+f"(d[0]), "+f"(d[1]), "+f"(d[2]), "+f"(d[3])
        : "r"(a[0]), "r"(a[1]), "r"(a[2]), "r"(a[3]), "r"(b0), "r"(b1));
}
__device__ __forceinline__ float ex2(float x) {
    float y; asm("ex2.approx.ftz.f32 %0, %1;" : "=f"(y) : "f"(x)); return y;
}
__device__ __forceinline__ uint32_t pkbf2(float lo, float hi) {
    uint32_t r;
    asm("cvt.rn.bf16x2.f32 %0, %1, %2;" : "=r"(r) : "f"(hi), "f"(lo));
    return r;
}
__device__ __forceinline__ float bf_hi(float x) {
    return __bfloat162float(__float2bfloat16(x));
}
__device__ __forceinline__ void split4(float4 v, __nv_bfloat162* hi, __nv_bfloat162* lo) {
    __nv_bfloat16 h0 = __float2bfloat16(v.x);
    __nv_bfloat16 h1 = __float2bfloat16(v.y);
    __nv_bfloat16 h2 = __float2bfloat16(v.z);
    __nv_bfloat16 h3 = __float2bfloat16(v.w);
    __nv_bfloat16 l0 = __float2bfloat16(v.x - __bfloat162float(h0));
    __nv_bfloat16 l1 = __float2bfloat16(v.y - __bfloat162float(h1));
    __nv_bfloat16 l2 = __float2bfloat16(v.z - __bfloat162float(h2));
    __nv_bfloat16 l3 = __float2bfloat16(v.w - __bfloat162float(h3));
    hi[0] = __nv_bfloat162(h0, h1); hi[1] = __nv_bfloat162(h2, h3);
    lo[0] = __nv_bfloat162(l0, l1); lo[1] = __nv_bfloat162(l2, l3);
}

// ---------------- fp32 -> bf16 hi/lo split kernels -----------------------------
__global__ void __launch_bounds__(256)
conv_x3(const float4* __restrict__ q, const float4* __restrict__ k,
        const float4* __restrict__ v)
{
    const int y = blockIdx.y;
    const float4* src = (y == 0) ? q : (y == 1) ? k : v;
    __nv_bfloat162* hi = (__nv_bfloat162*)(g_xh + (size_t)y * XELEMS);
    __nv_bfloat162* lo = (__nv_bfloat162*)(g_xl + (size_t)y * XELEMS);
    int i = blockIdx.x * 256 + threadIdx.x;
    split4(src[i], hi + i * 2, lo + i * 2);
}
__global__ void __launch_bounds__(256)
conv_w4(const float4* __restrict__ wq, const float4* __restrict__ wk,
        const float4* __restrict__ wv, const float4* __restrict__ wo)
{
    const int y = blockIdx.y;
    const float4* src = (y == 0) ? wq : (y == 1) ? wk : (y == 2) ? wv : wo;
    __nv_bfloat162* hi = (__nv_bfloat162*)(g_wh + (size_t)y * WELEMS);
    __nv_bfloat162* lo = (__nv_bfloat162*)(g_wl + (size_t)y * WELEMS);
    int i = blockIdx.x * 256 + threadIdx.x;
    split4(src[i], hi + i * 2, lo + i * 2);
}

// ---------------- HMMA bf16-split GEMM core ------------------------------------
#define GT_TILE  (128 * 80)
#define GT_STAGE (4 * GT_TILE)
#define GSMEM    (2 * GT_STAGE)

#define GEMM_ISSUE(ks, st) do {                                                 \
    const uint32_t ss = sb + (st) * GT_STAGE;                                   \
    size_t ga0 = ((size_t)(bm + r0) * DM + (ks) * 32 + kg0 * 8) * 2;            \
    size_t gb0 = ((size_t)(bn + r0) * DM + (ks) * 32 + kg0 * 8) * 2;            \
    size_t ga1 = ((size_t)(bm + r1) * DM + (ks) * 32 + kg1 * 8) * 2;            \
    size_t gb1 = ((size_t)(bn + r1) * DM + (ks) * 32 + kg1 * 8) * 2;            \
    uint32_t s0 = r0 * 80 + kg0 * 16, s1 = r1 * 80 + kg1 * 16;                  \
    cpa16(ss + 0 * GT_TILE + s0, pxh + ga0);                                    \
    cpa16(ss + 1 * GT_TILE + s0, pxl + ga0);                                    \
    cpa16(ss + 2 * GT_TILE + s0, pwh + gb0);                                    \
    cpa16(ss + 3 * GT_TILE + s0, pwl + gb0);                                    \
    cpa16(ss + 0 * GT_TILE + s1, pxh + ga1);                                    \
    cpa16(ss + 1 * GT_TILE + s1, pxl + ga1);                                    \
    cpa16(ss + 2 * GT_TILE + s1, pwh + gb1);                                    \
    cpa16(ss + 3 * GT_TILE + s1, pwl + gb1);                                    \
    asm volatile("cp.async.commit_group;" ::: "memory");                        \
} while (0)

// term-major MMA schedule: dependent-accumulator reuse distance = 16
#define GEMM_BODY()                                                             \
    GEMM_ISSUE(0, 0);                                                           \
    const int lrow = lane & 7;                                                  \
    const int sel  = lane >> 3;                                                 \
    const uint32_t fr_off = ((sel & 1) * 8 + lrow) * 80 + (sel >> 1) * 16;      \
    for (int ks = 0; ks < 32; ks++) {                                           \
        const int st = ks & 1;                                                  \
        if (ks + 1 < 32) {                                                      \
            GEMM_ISSUE(ks + 1, st ^ 1);                                         \
            asm volatile("cp.async.wait_group 1;" ::: "memory");                \
        } else {                                                                \
            asm volatile("cp.async.wait_group 0;" ::: "memory");                \
        }                                                                       \
        __syncthreads();                                                        \
        const uint32_t sAh = sb + st * GT_STAGE;                                \
        const uint32_t sAl = sAh + GT_TILE;                                     \
        const uint32_t sBh = sAh + 2 * GT_TILE;                                 \
        const uint32_t sBl = sAh + 3 * GT_TILE;                                 \
        _Pragma("unroll")                                                       \
        for (int k16 = 0; k16 < 2; k16++) {                                     \
            const uint32_t ko = fr_off + k16 * 32;                              \
            uint32_t ah[2][4], al[2][4], bh[4][4], bl[4][4];                    \
            _Pragma("unroll")                                                   \
            for (int mt = 0; mt < 2; mt++) {                                    \
                uint32_t base = (uint32_t)(wm * 32 + mt * 16) * 80 + ko;        \
                ldsm4(ah[mt], sAh + base);                                      \
                ldsm4(al[mt], sAl + base);                                      \
            }                                                                   \
            _Pragma("unroll")                                                   \
            for (int nq = 0; nq < 4; nq++) {                                    \
                uint32_t base = (uint32_t)(wn * 64 + nq * 16) * 80 + ko;        \
                ldsm4(bh[nq], sBh + base);                                      \
                ldsm4(bl[nq], sBl + base);                                      \
            }                                                                   \
            _Pragma("unroll")                                                   \
            for (int mt = 0; mt < 2; mt++)                                      \
                _Pragma("unroll")                                               \
                for (int nt = 0; nt < 8; nt++)                                  \
                    mma_bf16(acc[mt][nt], ah[mt], bh[nt >> 1][nt & 1],          \
                             bh[nt >> 1][(nt & 1) + 2]);                        \
            _Pragma("unroll")                                                   \
            for (int mt = 0; mt < 2; mt++)                                      \
                _Pragma("unroll")                                               \
                for (int nt = 0; nt < 8; nt++)                                  \
                    mma_bf16(acc[mt][nt], ah[mt], bl[nt >> 1][nt & 1],          \
                             bl[nt >> 1][(nt & 1) + 2]);                        \
            _Pragma("unroll")                                                   \
            for (int mt = 0; mt < 2; mt++)                                      \
                _Pragma("unroll")                                               \
                for (int nt = 0; nt < 8; nt++)                                  \
                    mma_bf16(acc[mt][nt], al[mt], bh[nt >> 1][nt & 1],          \
                             bh[nt >> 1][(nt & 1) + 2]);                        \
        }                                                                       \
        __syncthreads();                                                        \
    }

__global__ void __launch_bounds__(256)
gemm_qkv(const float* __restrict__ bq, const float* __restrict__ bk,
         const float* __restrict__ bv)
{
    extern __shared__ char smem[];
    const uint32_t sb = smem_u32(smem);

    const int tid  = threadIdx.x;
    const int lane = tid & 31;
    const int wid  = tid >> 5;
    const int wm   = wid & 3;
    const int wn   = wid >> 2;
    const int bm   = blockIdx.y << 7;
    const int bn   = blockIdx.x << 7;
    const int z    = blockIdx.z;

    const char* pxh = (const char*)(g_xh + (size_t)z * XELEMS);
    const char* pxl = (const char*)(g_xl + (size_t)z * XELEMS);
    const char* pwh = (const char*)(g_wh + (size_t)z * WELEMS);
    const char* pwl = (const char*)(g_wl + (size_t)z * WELEMS);
    const float* bias = (z == 0) ? bq : (z == 1) ? bk : bv;
    __nv_bfloat16* ph = (z == 0) ? g_qh : (z == 1) ? g_kh : g_vh;
    __nv_bfloat16* pl = (z == 0) ? g_ql : (z == 1) ? g_kl : g_vl;
    const float qs = (z == 0) ? 0.18033688011112042f : 1.0f;   // 0.125*log2(e)

    float acc[2][8][4];
#pragma unroll
    for (int mt = 0; mt < 2; mt++)
#pragma unroll
        for (int nt = 0; nt < 8; nt++)
#pragma unroll
            for (int e = 0; e < 4; e++) acc[mt][nt][e] = 0.0f;

    const int r0 = tid >> 2, kg0 = tid & 3;
    const int r1 = (tid + 256) >> 2, kg1 = (tid + 256) & 3;

    GEMM_BODY()

    const int gid = lane >> 2;
    const int t4  = lane & 3;
#pragma unroll
    for (int mt = 0; mt < 2; mt++) {
#pragma unroll
        for (int nt = 0; nt < 8; nt++) {
            const int n0 = bn + wn * 64 + nt * 8 + t4 * 2;
            const float b0 = bias[n0], b1 = bias[n0 + 1];
#pragma unroll
            for (int half = 0; half < 2; half++) {
                const int m = bm + wm * 32 + mt * 16 + gid + half * 8;
                float vx = (acc[mt][nt][half * 2 + 0] + b0) * qs;
                float vy = (acc[mt][nt][half * 2 + 1] + b1) * qs;
                const int bb = m >> 11;
                const int s  = m & (S_LEN - 1);
                const int h  = n0 >> 6;
                const int d  = n0 & 63;
                __nv_bfloat16 hx = __float2bfloat16(vx);
                __nv_bfloat16 hy = __float2bfloat16(vy);
                __nv_bfloat16 lx = __float2bfloat16(vx - __bfloat162float(hx));
                __nv_bfloat16 ly = __float2bfloat16(vy - __bfloat162float(hy));
                size_t off = (((size_t)(bb * NH + h) * S_LEN) + s) * DKH + d;
                *(__nv_bfloat162*)(ph + off) = __nv_bfloat162(hx, hy);
                *(__nv_bfloat162*)(pl + off) = __nv_bfloat162(lx, ly);
            }
        }
    }
}

__global__ void __launch_bounds__(256)
gemm_out(const float* __restrict__ bias, float* __restrict__ Yout)
{
    extern __shared__ char smem[];
    const uint32_t sb = smem_u32(smem);

    const int tid  = threadIdx.x;
    const int lane = tid & 31;
    const int wid  = tid >> 5;
    const int wm   = wid & 3;
    const int wn   = wid >> 2;
    const int bm   = blockIdx.y << 7;
    const int bn   = blockIdx.x << 7;

    const char* pxh = (const char*)g_xh;
    const char* pxl = (const char*)g_xl;
    const char* pwh = (const char*)(g_wh + 3 * WELEMS);
    const char* pwl = (const char*)(g_wl + 3 * WELEMS);

    float acc[2][8][4];
#pragma unroll
    for (int mt = 0; mt < 2; mt++)
#pragma unroll
        for (int nt = 0; nt < 8; nt++)
#pragma unroll
            for (int e = 0; e < 4; e++) acc[mt][nt][e] = 0.0f;

    const int r0 = tid >> 2, kg0 = tid & 3;
    const int r1 = (tid + 256) >> 2, kg1 = (tid + 256) & 3;

    GEMM_BODY()

    const int gid = lane >> 2;
    const int t4  = lane & 3;
#pragma unroll
    for (int mt = 0; mt < 2; mt++) {
#pragma unroll
        for (int nt = 0; nt < 8; nt++) {
            const int n0 = bn + wn * 64 + nt * 8 + t4 * 2;
            const float b0 = bias[n0], b1 = bias[n0 + 1];
#pragma unroll
            for (int half = 0; half < 2; half++) {
                const int m = bm + wm * 32 + mt * 16 + gid + half * 8;
                float2 val;
                val.x = acc[mt][nt][half * 2 + 0] + b0;
                val.y = acc[mt][nt][half * 2 + 1] + b1;
                *(float2*)(Yout + (size_t)m * DM + n0) = val;
            }
        }
    }
}

// ---------------- HMMA flash attention v4 --------------------------------------
// CTA = (bh, 64 q rows), 4 warps, 2 CTAs/SM, register-resident P,
// term-major MMA schedule, epilogue writes bf16 hi/lo straight into gemm X-bufs.
#define AT_S    144
#define AQ_TSZ  (64 * AT_S)
#define AKV_TSZ (128 * AT_S)
#define oQh 0
#define oQl (AQ_TSZ)
#define oKh (2 * AQ_TSZ)
#define oKl (2 * AQ_TSZ + AKV_TSZ)
#define oVh (2 * AQ_TSZ + 2 * AKV_TSZ)
#define oVl (2 * AQ_TSZ + 3 * AKV_TSZ)
#define ASMEM (2 * AQ_TSZ + 4 * AKV_TSZ)   // 92160

__global__ void __launch_bounds__(128, 2)
attn_mma()
{
    extern __shared__ char sm[];
    const uint32_t sb = smem_u32(sm);

    const int tid  = threadIdx.x;
    const int lane = tid & 31;
    const int w    = tid >> 5;
    const int gid  = lane >> 2;
    const int t4   = lane & 3;
    const int lrow = lane & 7;
    const int sel  = lane >> 3;
    const int bh   = blockIdx.y;
    const int q0   = blockIdx.x << 6;

    const size_t hb = (size_t)bh * S_LEN * DKH;
    const __nv_bfloat16* gqh = g_qh + hb;
    const __nv_bfloat16* gql = g_ql + hb;
    const __nv_bfloat16* gkh = g_kh + hb;
    const __nv_bfloat16* gkl = g_kl + hb;
    const __nv_bfloat16* gvh = g_vh + hb;
    const __nv_bfloat16* gvl = g_vl + hb;

#define AKV_ISSUE(offH, offL, srcH, srcL, row0) do {                            \
    _Pragma("unroll")                                                           \
    for (int p = 0; p < 8; p++) {                                               \
        int idx = tid + (p << 7);                                               \
        int r = idx >> 3, g = idx & 7;                                          \
        uint32_t so = (uint32_t)r * AT_S + g * 16;                              \
        size_t ge = (size_t)((row0) + r) * DKH + g * 8;                         \
        cpa16(sb + (offH) + so, (srcH) + ge);                                   \
        cpa16(sb + (offL) + so, (srcL) + ge);                                   \
    }                                                                           \
    asm volatile("cp.async.commit_group;" ::: "memory");                        \
} while (0)

    AKV_ISSUE(oKh, oKl, gkh, gkl, 0);
    AKV_ISSUE(oVh, oVl, gvh, gvl, 0);
#pragma unroll
    for (int p = 0; p < 4; p++) {
        int idx = tid + (p << 7);
        int r = idx >> 3, g = idx & 7;
        uint32_t so = (uint32_t)r * AT_S + g * 16;
        size_t ge = (size_t)(q0 + r) * DKH + g * 8;
        *(uint4*)(sm + oQh + so) = *(const uint4*)(gqh + ge);
        *(uint4*)(sm + oQl + so) = *(const uint4*)(gql + ge);
    }
    __syncthreads();

    const uint32_t frq = (uint32_t)((sel & 1) * 8 + lrow) * AT_S + (sel >> 1) * 16;
    uint32_t qfh[4][4], qfl[4][4];
#pragma unroll
    for (int k16 = 0; k16 < 4; k16++) {
        uint32_t a = sb + (uint32_t)(w * 16) * AT_S + frq + k16 * 32;
        ldsm4(qfh[k16], a + oQh);
        ldsm4(qfl[k16], a + oQl);
    }

    float m0 = -1e30f, m1 = -1e30f, l0 = 0.0f, l1 = 0.0f;
    float oacc[8][4];
#pragma unroll
    for (int nt = 0; nt < 8; nt++)
#pragma unroll
        for (int e = 0; e < 4; e++) oacc[nt][e] = 0.0f;

    for (int kt = 0; kt < S_LEN; kt += 128) {
        asm volatile("cp.async.wait_group 1;" ::: "memory");   // K(kt) ready
        __syncthreads();

        // ---- S = Q K^T : nb-pairs, term-major (dep distance 4) ----
        float sacc[16][4];
#pragma unroll
        for (int nt = 0; nt < 16; nt++)
#pragma unroll
            for (int e = 0; e < 4; e++) sacc[nt][e] = 0.0f;

#pragma unroll
        for (int k16 = 0; k16 < 4; k16++) {
#pragma unroll
            for (int nbp = 0; nbp < 4; nbp++) {
                uint32_t kbh[2][4], kbl[2][4];
#pragma unroll
                for (int i = 0; i < 2; i++) {
                    uint32_t off = sb + (uint32_t)((nbp * 2 + i) * 16) * AT_S + frq + k16 * 32;
                    ldsm4(kbh[i], off + oKh);
                    ldsm4(kbl[i], off + oKl);
                }
                float* s0 = sacc[nbp * 4 + 0];
                float* s1 = sacc[nbp * 4 + 1];
                float* s2 = sacc[nbp * 4 + 2];
                float* s3 = sacc[nbp * 4 + 3];
                mma_bf16(s0, qfh[k16], kbh[0][0], kbh[0][2]);
                mma_bf16(s1, qfh[k16], kbh[0][1], kbh[0][3]);
                mma_bf16(s2, qfh[k16], kbh[1][0], kbh[1][2]);
                mma_bf16(s3, qfh[k16], kbh[1][1], kbh[1][3]);
                mma_bf16(s0, qfh[k16], kbl[0][0], kbl[0][2]);
                mma_bf16(s1, qfh[k16], kbl[0][1], kbl[0][3]);
                mma_bf16(s2, qfh[k16], kbl[1][0], kbl[1][2]);
                mma_bf16(s3, qfh[k16], kbl[1][1], kbl[1][3]);
                mma_bf16(s0, qfl[k16], kbh[0][0], kbh[0][2]);
                mma_bf16(s1, qfl[k16], kbh[0][1], kbh[0][3]);
                mma_bf16(s2, qfl[k16], kbh[1][0], kbh[1][2]);
                mma_bf16(s3, qfl[k16], kbh[1][1], kbh[1][3]);
            }
        }
        __syncthreads();   // all warps done reading K

        if (kt + 128 < S_LEN)
            AKV_ISSUE(oKh, oKl, gkh, gkl, kt + 128);

        // NOTE: sacc index mapping changed: sacc[nbp*4 + i] covers kv cols
        // (nbp*2 + i/2)*16 + (i&1)*8. For softmax/PV we only need a consistent
        // bijection onto 128 cols, which this is (col block = idx via map below).

        // ---- online softmax ----
        float mx0 = -1e30f, mx1 = -1e30f;
#pragma unroll
        for (int nt = 0; nt < 16; nt++) {
            mx0 = fmaxf(mx0, fmaxf(sacc[nt][0], sacc[nt][1]));
            mx1 = fmaxf(mx1, fmaxf(sacc[nt][2], sacc[nt][3]));
        }
        mx0 = fmaxf(mx0, __shfl_xor_sync(0xffffffffu, mx0, 1));
        mx0 = fmaxf(mx0, __shfl_xor_sync(0xffffffffu, mx0, 2));
        mx1 = fmaxf(mx1, __shfl_xor_sync(0xffffffffu, mx1, 1));
        mx1 = fmaxf(mx1, __shfl_xor_sync(0xffffffffu, mx1, 2));
        const float nm0 = fmaxf(m0, mx0);
        const float nm1 = fmaxf(m1, mx1);

        float rs0 = 0.0f, rs1 = 0.0f;
#pragma unroll
        for (int nt = 0; nt < 16; nt++) {
            sacc[nt][0] = ex2(sacc[nt][0] - nm0);
            sacc[nt][1] = ex2(sacc[nt][1] - nm0);
            sacc[nt][2] = ex2(sacc[nt][2] - nm1);
            sacc[nt][3] = ex2(sacc[nt][3] - nm1);
            rs0 += sacc[nt][0] + sacc[nt][1];
            rs1 += sacc[nt][2] + sacc[nt][3];
        }
        rs0 += __shfl_xor_sync(0xffffffffu, rs0, 1);
        rs0 += __shfl_xor_sync(0xffffffffu, rs0, 2);
        rs1 += __shfl_xor_sync(0xffffffffu, rs1, 1);
        rs1 += __shfl_xor_sync(0xffffffffu, rs1, 2);

        const float c0 = ex2(m0 - nm0);
        const float c1 = ex2(m1 - nm1);
        l0 = l0 * c0 + rs0;  m0 = nm0;
        l1 = l1 * c1 + rs1;  m1 = nm1;
#pragma unroll
        for (int nt = 0; nt < 8; nt++) {
            oacc[nt][0] *= c0; oacc[nt][1] *= c0;
            oacc[nt][2] *= c1; oacc[nt][3] *= c1;
        }

        asm volatile("cp.async.wait_group 1;" ::: "memory");   // V(kt) ready
        __syncthreads();

        // ---- O += P V : per j (16 kv rows), term-major across 8 oacc ----
        // kv col block 16j maps to sacc indices: j = nbp*2 + jj where fragment
        // pair (sacc[nbp*4 + 2*jj], sacc[nbp*4 + 2*jj + 1]) covers cols 16j..16j+15.
#pragma unroll
        for (int j = 0; j < 8; j++) {
            const int si = (j >> 1) * 4 + (j & 1) * 2;   // sacc base index
            float h00 = bf_hi(sacc[si][0]),   h01 = bf_hi(sacc[si][1]);
            float h02 = bf_hi(sacc[si][2]),   h03 = bf_hi(sacc[si][3]);
            float h10 = bf_hi(sacc[si+1][0]), h11 = bf_hi(sacc[si+1][1]);
            float h12 = bf_hi(sacc[si+1][2]), h13 = bf_hi(sacc[si+1][3]);
            uint32_t afh[4], afl[4];
            afh[0] = pkbf2(h00, h01);
            afh[1] = pkbf2(h02, h03);
            afh[2] = pkbf2(h10, h11);
            afh[3] = pkbf2(h12, h13);
            afl[0] = pkbf2(sacc[si][0]   - h00, sacc[si][1]   - h01);
            afl[1] = pkbf2(sacc[si][2]   - h02, sacc[si][3]   - h03);
            afl[2] = pkbf2(sacc[si+1][0] - h10, sacc[si+1][1] - h11);
            afl[3] = pkbf2(sacc[si+1][2] - h12, sacc[si+1][3] - h13);

            uint32_t vbh[4][4], vbl[4][4];
            const uint32_t vrow = sb + (uint32_t)(j * 16 + (lane & 15)) * AT_S;
#pragma unroll
            for (int dg = 0; dg < 4; dg++) {
                uint32_t va = vrow + (uint32_t)(dg * 2 + (lane >> 4)) * 16;
                ldsm4t(vbh[dg], va + oVh);
                ldsm4t(vbl[dg], va + oVl);
            }
#pragma unroll
            for (int dg = 0; dg < 4; dg++) {
                mma_bf16(oacc[dg * 2 + 0], afh, vbh[dg][0], vbh[dg][1]);
                mma_bf16(oacc[dg * 2 + 1], afh, vbh[dg][2], vbh[dg][3]);
            }
#pragma unroll
            for (int dg = 0; dg < 4; dg++) {
                mma_bf16(oacc[dg * 2 + 0], afh, vbl[dg][0], vbl[dg][1]);
                mma_bf16(oacc[dg * 2 + 1], afh, vbl[dg][2], vbl[dg][3]);
            }
#pragma unroll
            for (int dg = 0; dg < 4; dg++) {
                mma_bf16(oacc[dg * 2 + 0], afl, vbh[dg][0], vbh[dg][1]);
                mma_bf16(oacc[dg * 2 + 1], afl, vbh[dg][2], vbh[dg][3]);
            }
        }
        __syncthreads();   // all warps done reading V

        if (kt + 128 < S_LEN)
            AKV_ISSUE(oVh, oVl, gvh, gvl, kt + 128);
    }

    // ---- epilogue: normalize, split to bf16 hi/lo, write gemm X slot 0 ----
    const int b = bh >> 4;
    const int h = bh & 15;
    const float inv0 = 1.0f / l0;
    const float inv1 = 1.0f / l1;
    const int r0 = q0 + w * 16 + gid;
    const int r1 = r0 + 8;
#pragma unroll
    for (int nt = 0; nt < 8; nt++) {
        const int col = (h << 6) + nt * 8 + t4 * 2;
        float v0x = oacc[nt][0] * inv0, v0y = oacc[nt][1] * inv0;
        float v1x = oacc[nt][2] * inv1, v1y = oacc[nt][3] * inv1;
        float h0x = bf_hi(v0x), h0y = bf_hi(v0y);
        float h1x = bf_hi(v1x), h1y = bf_hi(v1y);
        size_t o0 = (size_t)(b * S_LEN + r0) * DM + col;
        size_t o1 = (size_t)(b * S_LEN + r1) * DM + col;
        *(uint32_t*)(g_xh + o0) = pkbf2(h0x, h0y);
        *(uint32_t*)(g_xl + o0) = pkbf2(v0x - h0x, v0y - h0y);
        *(uint32_t*)(g_xh + o1) = pkbf2(h1x, h1y);
        *(uint32_t*)(g_xl + o1) = pkbf2(v1x - h1x, v1y - h1y);
    }
#undef AKV_ISSUE
}

// ---------------------------------------------------------------------------
extern "C" void kernel_launch(void* const* d_in, const int* in_sizes, int n_in,
                              void* d_out, int out_size)
{
    const float* q  = (const float*)d_in[0];
    const float* k  = (const float*)d_in[1];
    const float* v  = (const float*)d_in[2];
    const float* wq = (const float*)d_in[3];
    const float* bq = (const float*)d_in[4];
    const float* wk = (const float*)d_in[5];
    const float* bk = (const float*)d_in[6];
    const float* wv = (const float*)d_in[7];
    const float* bv = (const float*)d_in[8];
    const float* wo = (const float*)d_in[9];
    const float* bo = (const float*)d_in[10];
    float* out = (float*)d_out;

    cudaFuncSetAttribute(gemm_qkv, cudaFuncAttributeMaxDynamicSharedMemorySize, GSMEM);
    cudaFuncSetAttribute(gemm_out, cudaFuncAttributeMaxDynamicSharedMemorySize, GSMEM);
    cudaFuncSetAttribute(attn_mma, cudaFuncAttributeMaxDynamicSharedMemorySize, ASMEM);

    const int bx = (int)(XELEMS / 4 / 256);   // 4096
    const int bw = (int)(WELEMS / 4 / 256);   // 1024

    conv_x3<<<dim3(bx, 3), 256>>>((const float4*)q, (const float4*)k, (const float4*)v);
    conv_w4<<<dim3(bw, 4), 256>>>((const float4*)wq, (const float4*)wk,
                                  (const float4*)wv, (const float4*)wo);
    gemm_qkv<<<dim3(8, 32, 3), 256, GSMEM>>>(bq, bk, bv);
    attn_mma<<<dim3(S_LEN / 64, B_SZ * NH), 128, ASMEM>>>();
    gemm_out<<<dim3(8, 32), 256, GSMEM>>>(bo, out);
}